// round 1
// baseline (speedup 1.0000x reference)
#include <cuda_runtime.h>
#include <math.h>

#define DD 256
#define LL 128
#define NEG_SLOPE 0.2f
#define LN_EPS 1e-5f

// smem layout (floats):
//  A_s   [128*256]            32768 f
//  W2T   [256*65]             16640 f   (padded rows -> conflict-free)
//  qb_s  [256], w_s[256], x_s[256], y_s[256], ctx_s[256]   1280 f
//  s_arr [128], p_arr[128]     256 f
//  red   [32]
//  act   [128] ints, cnts[8] ints
static const int SMEM_FLOATS = 32768 + 16640 + 1280 + 256 + 32;
static const int SMEM_BYTES  = SMEM_FLOATS * 4 + (128 + 8) * 4;

__global__ __launch_bounds__(256, 1)
void gnn_agg_kernel(const float* __restrict__ mol,     // [B,D]
                    const float* __restrict__ atom,    // [B,L,D]
                    const float* __restrict__ attend,  // [B,L,1]
                    const float* __restrict__ W1,      // [D,D]
                    const float* __restrict__ b1,      // [D]
                    const float* __restrict__ W2,      // [D,D]
                    const float* __restrict__ b2,      // [D]
                    const float* __restrict__ w_align, // [D,1]
                    const float* __restrict__ b_align, // [1]
                    const float* __restrict__ gamma_,  // [D]
                    const float* __restrict__ beta_,   // [D]
                    float* __restrict__ out)           // [B,D]
{
    extern __shared__ float sm[];
    float* A_s   = sm;                     // active atom rows, compacted
    float* W2T   = sm + 32768;             // [k=256][dl=65]
    float* qb_s  = W2T + 16640;            // q + b1 + b2
    float* w_s   = qb_s + DD;
    float* x_s   = w_s  + DD;
    float* y_s   = x_s  + DD;
    float* ctx_s = y_s  + DD;
    float* s_arr = ctx_s + DD;             // scores per active atom
    float* p_arr = s_arr + LL;             // softmax probs -> attn
    float* red   = p_arr + LL;             // reduction scratch
    int*   act   = (int*)(red + 32);       // active atom indices
    int*   cnts  = act + LL;

    const int b    = blockIdx.x;
    const int tid  = threadIdx.x;
    const int lane = tid & 31;
    const int wid  = tid >> 5;

    // ---- active-atom compaction (deterministic, ballot-based) ----
    int flag = 0;
    if (tid < LL) flag = (attend[(long)b * LL + tid] > 0.5f) ? 1 : 0;
    unsigned bm = __ballot_sync(0xffffffffu, flag);
    if (tid < LL && lane == 0) cnts[wid] = __popc(bm);
    __syncthreads();
    if (tid < LL && flag) {
        int base = 0;
        for (int w = 0; w < wid; ++w) base += cnts[w];
        act[base + __popc(bm & ((1u << lane) - 1u))] = tid;
    }
    if (tid == 0) cnts[4] = cnts[0] + cnts[1] + cnts[2] + cnts[3];

    x_s[tid] = mol[(long)b * DD + tid];
    w_s[tid] = w_align[tid];
    __syncthreads();
    const int nact = cnts[4];

    // ---- q[d] = x @ W1.T + b1 ;  qb = q + b2 (pre-fold nb bias) ----
    {
        float acc = 0.f;
        const float4* w4 = (const float4*)(W1 + (long)tid * DD);
        #pragma unroll 8
        for (int k4 = 0; k4 < DD / 4; ++k4) {
            float4 wv = w4[k4];
            acc += x_s[4*k4+0]*wv.x + x_s[4*k4+1]*wv.y
                 + x_s[4*k4+2]*wv.z + x_s[4*k4+3]*wv.w;
        }
        qb_s[tid] = acc + b1[tid] + b2[tid];
    }

    // ---- load active atom rows into smem (coalesced) ----
    for (int idx = tid; idx < nact * DD; idx += 256) {
        int a = idx >> 8, k = idx & 255;
        A_s[idx] = atom[((long)b * LL + act[a]) * DD + k];
    }
    for (int a = tid; a < nact; a += 256) s_arr[a] = b_align[0];

    // ---- scores: s[l] = sum_d w_align[d]*leakyrelu(qb[d] + (A@W2.T)[l,d]) ----
    // chunk W2 over d in 4 x 64, transposed into smem
    for (int c = 0; c < 4; ++c) {
        const int d0 = c * 64;
        __syncthreads();   // fences A_s/s_arr writes (c==0) & W2T reuse (c>0)
        for (int idx = tid; idx < 64 * DD; idx += 256) {
            int dl = idx >> 8, k = idx & 255;
            W2T[k * 65 + dl] = W2[(long)(d0 + dl) * DD + k];
        }
        __syncthreads();

        const float qv1 = qb_s[d0 + lane];
        const float qv2 = qb_s[d0 + lane + 32];
        const float wv1 = w_s[d0 + lane];
        const float wv2 = w_s[d0 + lane + 32];

        for (int t0 = 0; t0 < nact; t0 += 32) {
            const int abase = t0 + wid * 4;
            if (abase >= nact) continue;   // no syncs inside -> safe
            const int na = nact - abase;
            const float* A0 = A_s + (long)abase * DD;
            const float* A1 = A_s + (long)min(abase + 1, nact - 1) * DD;
            const float* A2 = A_s + (long)min(abase + 2, nact - 1) * DD;
            const float* A3 = A_s + (long)min(abase + 3, nact - 1) * DD;

            float a00=0.f,a01=0.f,a10=0.f,a11=0.f,a20=0.f,a21=0.f,a30=0.f,a31=0.f;
            #pragma unroll 4
            for (int k = 0; k < DD; ++k) {
                const float wA = W2T[k * 65 + lane];
                const float wB = W2T[k * 65 + lane + 32];
                const float f0 = A0[k], f1 = A1[k], f2 = A2[k], f3 = A3[k];
                a00 += f0 * wA; a01 += f0 * wB;
                a10 += f1 * wA; a11 += f1 * wB;
                a20 += f2 * wA; a21 += f2 * wB;
                a30 += f3 * wA; a31 += f3 * wB;
            }
            float accs[4][2] = {{a00,a01},{a10,a11},{a20,a21},{a30,a31}};
            #pragma unroll
            for (int j = 0; j < 4; ++j) {
                if (j < na) {
                    float v1 = qv1 + accs[j][0]; v1 = (v1 >= 0.f) ? v1 : NEG_SLOPE * v1;
                    float v2 = qv2 + accs[j][1]; v2 = (v2 >= 0.f) ? v2 : NEG_SLOPE * v2;
                    float contrib = v1 * wv1 + v2 * wv2;
                    #pragma unroll
                    for (int off = 16; off; off >>= 1)
                        contrib += __shfl_down_sync(0xffffffffu, contrib, off);
                    if (lane == 0) s_arr[abase + j] += contrib;
                }
            }
        }
    }
    __syncthreads();

    // ---- softmax over active atoms (exact: masked atoms underflow to 0 in ref) ----
    if (nact > 0) {
        float v = (tid < nact) ? s_arr[tid] : -INFINITY;
        float t = v;
        #pragma unroll
        for (int off = 16; off; off >>= 1)
            t = fmaxf(t, __shfl_xor_sync(0xffffffffu, t, off));
        if (lane == 0) red[wid] = t;
        __syncthreads();
        float mx = red[0];
        #pragma unroll
        for (int w = 1; w < 8; ++w) mx = fmaxf(mx, red[w]);
        __syncthreads();

        float p = (tid < nact) ? __expf(v - mx) : 0.f;
        float ts = p;
        #pragma unroll
        for (int off = 16; off; off >>= 1)
            ts += __shfl_xor_sync(0xffffffffu, ts, off);
        if (lane == 0) red[wid] = ts;
        __syncthreads();
        float Z = red[0];
        #pragma unroll
        for (int w = 1; w < 8; ++w) Z += red[w];
        if (tid < nact) p_arr[tid] = p / Z;
        __syncthreads();
    }

    // ---- y[k] = sum_l attn[l] * A[l,k] ----
    {
        float acc = 0.f;
        for (int a = 0; a < nact; ++a)
            acc += p_arr[a] * A_s[(long)a * DD + tid];
        y_s[tid] = acc;
    }
    __syncthreads();

    // ---- ctx[d] = y @ W2.T + (sum attn == 1)*b2 ----
    {
        float acc = (nact > 0) ? b2[tid] : 0.f;
        const float4* w4 = (const float4*)(W2 + (long)tid * DD);
        #pragma unroll 8
        for (int k4 = 0; k4 < DD / 4; ++k4) {
            float4 wv = w4[k4];
            acc += y_s[4*k4+0]*wv.x + y_s[4*k4+1]*wv.y
                 + y_s[4*k4+2]*wv.z + y_s[4*k4+3]*wv.w;
        }
        ctx_s[tid] = acc;
    }
    __syncthreads();

    // ---- LayerNorm over D ----
    {
        float v = ctx_s[tid];
        float s1 = v;
        #pragma unroll
        for (int off = 16; off; off >>= 1)
            s1 += __shfl_xor_sync(0xffffffffu, s1, off);
        if (lane == 0) red[wid] = s1;
        __syncthreads();
        float total = red[0];
        #pragma unroll
        for (int w = 1; w < 8; ++w) total += red[w];
        const float mu = total * (1.f / DD);
        const float dv = v - mu;
        __syncthreads();

        float s2 = dv * dv;
        #pragma unroll
        for (int off = 16; off; off >>= 1)
            s2 += __shfl_xor_sync(0xffffffffu, s2, off);
        if (lane == 0) red[wid] = s2;
        __syncthreads();
        float tot2 = red[0];
        #pragma unroll
        for (int w = 1; w < 8; ++w) tot2 += red[w];
        const float var = tot2 * (1.f / DD);
        out[(long)b * DD + tid] = dv * rsqrtf(var + LN_EPS) * gamma_[tid] + beta_[tid];
    }
}

extern "C" void kernel_launch(void* const* d_in, const int* in_sizes, int n_in,
                              void* d_out, int out_size)
{
    const float* mol     = (const float*)d_in[0];
    const float* atom    = (const float*)d_in[1];
    const float* attend  = (const float*)d_in[2];
    // d_in[3] = softmax_mask: derived exactly from attend, unused
    const float* W1      = (const float*)d_in[4];
    const float* b1      = (const float*)d_in[5];
    const float* W2      = (const float*)d_in[6];
    const float* b2      = (const float*)d_in[7];
    const float* w_align = (const float*)d_in[8];
    const float* b_align = (const float*)d_in[9];
    const float* gamma_  = (const float*)d_in[10];
    const float* beta_   = (const float*)d_in[11];
    float* out = (float*)d_out;

    const int B = in_sizes[0] / DD;

    cudaFuncSetAttribute(gnn_agg_kernel,
                         cudaFuncAttributeMaxDynamicSharedMemorySize, SMEM_BYTES);
    gnn_agg_kernel<<<B, 256, SMEM_BYTES>>>(mol, atom, attend, W1, b1, W2, b2,
                                           w_align, b_align, gamma_, beta_, out);
}

// round 2
// speedup vs baseline: 1.3878x; 1.3878x over previous
#include <cuda_runtime.h>
#include <math.h>

#define DD 256
#define LL 128
#define NEG_SLOPE 0.2f
#define LN_EPS 1e-5f

// smem layout (floats):
//  A_s    [128*256]   32768
//  W2c    [64*260]    16640   (padded rows -> conflict-free float4)
//  qb_s/w_s/x_s/y_s/ctx_s [256] each = 1280
//  s_part [2*128]       256
//  p_arr  [128]         128
//  red    [32]
//  act    [128] int, cnts[8] int
static const int SMEM_FLOATS = 32768 + 16640 + 1280 + 256 + 128 + 32;
static const int SMEM_BYTES  = SMEM_FLOATS * 4 + (128 + 8) * 4;

__global__ __launch_bounds__(256, 1)
void gnn_agg_kernel(const float* __restrict__ mol,     // [B,D]
                    const float* __restrict__ atom,    // [B,L,D]
                    const float* __restrict__ attend,  // [B,L,1]
                    const float* __restrict__ W1,      // [D,D]
                    const float* __restrict__ b1,      // [D]
                    const float* __restrict__ W2,      // [D,D]
                    const float* __restrict__ b2,      // [D]
                    const float* __restrict__ w_align, // [D,1]
                    const float* __restrict__ b_align, // [1]
                    const float* __restrict__ gamma_,  // [D]
                    const float* __restrict__ beta_,   // [D]
                    float* __restrict__ out)           // [B,D]
{
    extern __shared__ float sm[];
    float* A_s    = sm;                     // compacted active atom rows
    float* W2c    = sm + 32768;             // [64][260] natural row layout
    float* qb_s   = W2c + 16640;            // q + b1 + b2
    float* w_s    = qb_s + DD;
    float* x_s    = w_s  + DD;
    float* y_s    = x_s  + DD;
    float* ctx_s  = y_s  + DD;
    float* s_part = ctx_s + DD;             // [2][128] per-dhalf score partials
    float* p_arr  = s_part + 2 * LL;
    float* red    = p_arr + LL;
    int*   act    = (int*)(red + 32);
    int*   cnts   = act + LL;

    const int b    = blockIdx.x;
    const int tid  = threadIdx.x;
    const int lane = tid & 31;
    const int wid  = tid >> 5;

    // ---- active-atom compaction ----
    int flag = 0;
    if (tid < LL) flag = (attend[(long)b * LL + tid] > 0.5f) ? 1 : 0;
    unsigned bm = __ballot_sync(0xffffffffu, flag);
    if (tid < LL && lane == 0) cnts[wid] = __popc(bm);
    __syncthreads();
    if (tid < LL && flag) {
        int base = 0;
        for (int w = 0; w < wid; ++w) base += cnts[w];
        act[base + __popc(bm & ((1u << lane) - 1u))] = tid;
    }
    if (tid == 0) cnts[4] = cnts[0] + cnts[1] + cnts[2] + cnts[3];

    x_s[tid] = mol[(long)b * DD + tid];
    w_s[tid] = w_align[tid];
    s_part[tid] = 0.f;          // covers all 2*128 entries
    __syncthreads();
    const int nact = cnts[4];
    const float bal = b_align[0];

    // ---- qb[d] = x @ W1.T + b1 + b2 ----
    {
        float acc = 0.f;
        const float4* w4 = (const float4*)(W1 + (long)tid * DD);
        #pragma unroll 8
        for (int k4 = 0; k4 < DD / 4; ++k4) {
            float4 wv = w4[k4];
            acc += x_s[4*k4+0]*wv.x + x_s[4*k4+1]*wv.y
                 + x_s[4*k4+2]*wv.z + x_s[4*k4+3]*wv.w;
        }
        qb_s[tid] = acc + b1[tid] + b2[tid];
    }

    // ---- load active atom rows (float4, coalesced) ----
    {
        float4* A4w = (float4*)A_s;
        const float4* atom4 = (const float4*)atom;
        for (int idx = tid; idx < nact * 64; idx += 256) {
            int a = idx >> 6, k4 = idx & 63;
            A4w[idx] = atom4[((long)b * LL + act[a]) * 64 + k4];
        }
    }

    // ---- scores: acc[a][d] = (A@W2.T)[a,d], then leakyrelu(qb+acc)·w_align ----
    // warp roles: dhalf = wid&1 (32 d's, d = c*64 + dhalf*32 + lane),
    //             aq = wid>>1 (atom groups a0 = aq*8 + 32t)
    const int dhalf = wid & 1;
    const int aq    = wid >> 1;
    const float4* A4 = (const float4*)A_s;

    for (int c = 0; c < 4; ++c) {
        __syncthreads();   // compute(c-1) done before restaging W2c
        {
            const float4* Wg  = (const float4*)(W2 + (long)c * 64 * DD);
            float4*       Wc4 = (float4*)W2c;
            for (int idx = tid; idx < 64 * 64; idx += 256) {
                int r = idx >> 6, k4 = idx & 63;
                Wc4[r * 65 + k4] = Wg[r * 64 + k4];
            }
        }
        __syncthreads();

        const int   d  = c * 64 + dhalf * 32 + lane;
        const float qv = qb_s[d];
        const float wv = w_s[d];
        const float4* Wrow = (const float4*)W2c + (dhalf * 32 + lane) * 65;

        for (int a0 = aq * 8; a0 < nact; a0 += 32) {
            int roff[8];
            #pragma unroll
            for (int j = 0; j < 8; ++j)
                roff[j] = min(a0 + j, nact - 1) * 64;

            float acc[8] = {0.f,0.f,0.f,0.f,0.f,0.f,0.f,0.f};
            #pragma unroll 4
            for (int k4 = 0; k4 < 64; ++k4) {
                const float4 w = Wrow[k4];
                #pragma unroll
                for (int j = 0; j < 8; ++j) {
                    const float4 av = A4[roff[j] + k4];   // broadcast LDS.128
                    acc[j] += av.x * w.x + av.y * w.y + av.z * w.z + av.w * w.w;
                }
            }
            #pragma unroll
            for (int j = 0; j < 8; ++j) {
                float v = qv + acc[j];
                v = (v >= 0.f) ? v : NEG_SLOPE * v;
                float contrib = v * wv;
                #pragma unroll
                for (int off = 16; off; off >>= 1)
                    contrib += __shfl_xor_sync(0xffffffffu, contrib, off);
                if (lane == 0 && a0 + j < nact)
                    s_part[dhalf * LL + a0 + j] += contrib;   // unique writer warp
            }
        }
    }
    __syncthreads();

    // ---- softmax over active atoms (masked atoms are exactly 0 in ref) ----
    if (nact > 0) {
        float v = (tid < nact) ? (bal + s_part[tid] + s_part[LL + tid]) : -INFINITY;
        float t = v;
        #pragma unroll
        for (int off = 16; off; off >>= 1)
            t = fmaxf(t, __shfl_xor_sync(0xffffffffu, t, off));
        if (lane == 0) red[wid] = t;
        __syncthreads();
        float mx = red[0];
        #pragma unroll
        for (int w = 1; w < 8; ++w) mx = fmaxf(mx, red[w]);
        __syncthreads();

        float p = (tid < nact) ? __expf(v - mx) : 0.f;
        float ts = p;
        #pragma unroll
        for (int off = 16; off; off >>= 1)
            ts += __shfl_xor_sync(0xffffffffu, ts, off);
        if (lane == 0) red[wid] = ts;
        __syncthreads();
        float Z = red[0];
        #pragma unroll
        for (int w = 1; w < 8; ++w) Z += red[w];
        if (tid < nact) p_arr[tid] = p / Z;
        __syncthreads();
    }

    // ---- y[k] = sum_a attn[a] * A[a,k] ----
    {
        float acc = 0.f;
        for (int a = 0; a < nact; ++a)
            acc += p_arr[a] * A_s[(long)a * DD + tid];
        y_s[tid] = acc;
    }
    __syncthreads();

    // ---- ctx[d] = y @ W2.T + b2 ----
    {
        float acc = (nact > 0) ? b2[tid] : 0.f;
        const float4* w4 = (const float4*)(W2 + (long)tid * DD);
        #pragma unroll 8
        for (int k4 = 0; k4 < DD / 4; ++k4) {
            float4 wv = w4[k4];
            acc += y_s[4*k4+0]*wv.x + y_s[4*k4+1]*wv.y
                 + y_s[4*k4+2]*wv.z + y_s[4*k4+3]*wv.w;
        }
        ctx_s[tid] = acc;
    }
    __syncthreads();

    // ---- LayerNorm over D ----
    {
        float v = ctx_s[tid];
        float s1 = v;
        #pragma unroll
        for (int off = 16; off; off >>= 1)
            s1 += __shfl_xor_sync(0xffffffffu, s1, off);
        if (lane == 0) red[wid] = s1;
        __syncthreads();
        float total = red[0];
        #pragma unroll
        for (int w = 1; w < 8; ++w) total += red[w];
        const float mu = total * (1.f / DD);
        const float dv = v - mu;
        __syncthreads();

        float s2 = dv * dv;
        #pragma unroll
        for (int off = 16; off; off >>= 1)
            s2 += __shfl_xor_sync(0xffffffffu, s2, off);
        if (lane == 0) red[wid] = s2;
        __syncthreads();
        float tot2 = red[0];
        #pragma unroll
        for (int w = 1; w < 8; ++w) tot2 += red[w];
        const float var = tot2 * (1.f / DD);
        out[(long)b * DD + tid] = dv * rsqrtf(var + LN_EPS) * gamma_[tid] + beta_[tid];
    }
}

extern "C" void kernel_launch(void* const* d_in, const int* in_sizes, int n_in,
                              void* d_out, int out_size)
{
    const float* mol     = (const float*)d_in[0];
    const float* atom    = (const float*)d_in[1];
    const float* attend  = (const float*)d_in[2];
    const float* W1      = (const float*)d_in[4];
    const float* b1      = (const float*)d_in[5];
    const float* W2      = (const float*)d_in[6];
    const float* b2      = (const float*)d_in[7];
    const float* w_align = (const float*)d_in[8];
    const float* b_align = (const float*)d_in[9];
    const float* gamma_  = (const float*)d_in[10];
    const float* beta_   = (const float*)d_in[11];
    float* out = (float*)d_out;

    const int B = in_sizes[0] / DD;

    cudaFuncSetAttribute(gnn_agg_kernel,
                         cudaFuncAttributeMaxDynamicSharedMemorySize, SMEM_BYTES);
    gnn_agg_kernel<<<B, 256, SMEM_BYTES>>>(mol, atom, attend, W1, b1, W2, b2,
                                           w_align, b_align, gamma_, beta_, out);
}

// round 3
// speedup vs baseline: 1.4644x; 1.0552x over previous
#include <cuda_runtime.h>
#include <math.h>

#define DD 256
#define LL 128
#define NEG_SLOPE 0.2f
#define LN_EPS 1e-5f

// smem (floats): A_s 32768 | W2c 64*260=16640 | qb/w/x/y/ctx 5*256 | s_arr 128
//                p_arr 128 | red 32  (+ act[128] & cnts[8] ints)
static const int SMEM_FLOATS = 32768 + 16640 + 1280 + 128 + 128 + 32;
static const int SMEM_BYTES  = SMEM_FLOATS * 4 + (128 + 8) * 4;

__global__ __launch_bounds__(256, 1)
void gnn_agg_kernel(const float* __restrict__ mol,     // [B,D]
                    const float* __restrict__ atom,    // [B,L,D]
                    const float* __restrict__ attend,  // [B,L,1]
                    const float* __restrict__ W1,      // [D,D]
                    const float* __restrict__ b1,      // [D]
                    const float* __restrict__ W2,      // [D,D]
                    const float* __restrict__ b2,      // [D]
                    const float* __restrict__ w_align, // [D,1]
                    const float* __restrict__ b_align, // [1]
                    const float* __restrict__ gamma_,  // [D]
                    const float* __restrict__ beta_,   // [D]
                    float* __restrict__ out)           // [B,D]
{
    extern __shared__ float sm[];
    float* A_s   = sm;                      // compacted active atom rows
    float* W2c   = sm + 32768;              // [64][260] padded, natural rows
    float* qb_s  = W2c + 16640;             // q + b1 + b2
    float* w_s   = qb_s + DD;
    float* x_s   = w_s  + DD;
    float* y_s   = x_s  + DD;
    float* ctx_s = y_s  + DD;
    float* s_arr = ctx_s + DD;              // final scores
    float* p_arr = s_arr + LL;
    float* red   = p_arr + LL;
    int*   act   = (int*)(red + 32);
    int*   cnts  = act + LL;

    const int b    = blockIdx.x;
    const int tid  = threadIdx.x;
    const int lane = tid & 31;
    const int wid  = tid >> 5;

    // ---- active-atom compaction ----
    int flag = 0;
    if (tid < LL) flag = (attend[(long)b * LL + tid] > 0.5f) ? 1 : 0;
    unsigned bm = __ballot_sync(0xffffffffu, flag);
    if (tid < LL && lane == 0) cnts[wid] = __popc(bm);
    __syncthreads();
    if (tid < LL && flag) {
        int base = 0;
        for (int w = 0; w < wid; ++w) base += cnts[w];
        act[base + __popc(bm & ((1u << lane) - 1u))] = tid;
    }
    if (tid == 0) cnts[4] = cnts[0] + cnts[1] + cnts[2] + cnts[3];

    x_s[tid] = mol[(long)b * DD + tid];
    w_s[tid] = w_align[tid];
    __syncthreads();
    const int nact = cnts[4];
    const float bal = b_align[0];

    // ---- load active atom rows into smem (float4, coalesced) ----
    {
        float4* A4w = (float4*)A_s;
        const float4* atom4 = (const float4*)atom;
        for (int idx = tid; idx < nact * 64; idx += 256) {
            int a = idx >> 6, k4 = idx & 63;
            A4w[idx] = atom4[((long)b * LL + act[a]) * 64 + k4];
        }
    }

    // ---- qb[d] = x @ W1.T + b1 + b2 ----
    {
        float acc = 0.f;
        const float4* w4 = (const float4*)(W1 + (long)tid * DD);
        #pragma unroll 8
        for (int k4 = 0; k4 < DD / 4; ++k4) {
            float4 wv = w4[k4];
            acc += x_s[4*k4+0]*wv.x + x_s[4*k4+1]*wv.y
                 + x_s[4*k4+2]*wv.z + x_s[4*k4+3]*wv.w;
        }
        qb_s[tid] = acc + b1[tid] + b2[tid];
    }

    // ---- score GEMM: each warp owns 16 atoms x all 64 d's of each chunk ----
    const int a0 = wid * 16;
    int roff[16];
    #pragma unroll
    for (int j = 0; j < 16; ++j)
        roff[j] = (nact > 0 ? min(a0 + j, nact - 1) : 0) * 64;

    float sc[16];
    #pragma unroll
    for (int j = 0; j < 16; ++j) sc[j] = 0.f;

    const float4* A4 = (const float4*)A_s;

    for (int c = 0; c < 4; ++c) {
        __syncthreads();   // previous chunk's compute done before restage
        {
            const float4* Wg  = (const float4*)(W2 + (long)c * 64 * DD);
            float4*       Wc4 = (float4*)W2c;
            for (int idx = tid; idx < 64 * 64; idx += 256) {
                int r = idx >> 6, k4 = idx & 63;
                Wc4[r * 65 + k4] = Wg[r * 64 + k4];
            }
        }
        __syncthreads();

        if (a0 < nact) {
            const float qv1 = qb_s[c * 64 + lane];
            const float qv2 = qb_s[c * 64 + 32 + lane];
            const float wv1 = w_s[c * 64 + lane];
            const float wv2 = w_s[c * 64 + 32 + lane];
            const float4* Wr1 = (const float4*)W2c + lane * 65;
            const float4* Wr2 = (const float4*)W2c + (lane + 32) * 65;

            float acc0[16], acc1[16];
            #pragma unroll
            for (int j = 0; j < 16; ++j) { acc0[j] = 0.f; acc1[j] = 0.f; }

            #pragma unroll 2
            for (int k4 = 0; k4 < 64; ++k4) {
                const float4 w1 = Wr1[k4];
                const float4 w2 = Wr2[k4];
                #pragma unroll
                for (int j = 0; j < 16; ++j) {
                    const float4 av = A4[roff[j] + k4];   // broadcast
                    acc0[j] += av.x*w1.x + av.y*w1.y + av.z*w1.z + av.w*w1.w;
                    acc1[j] += av.x*w2.x + av.y*w2.y + av.z*w2.z + av.w*w2.w;
                }
            }
            #pragma unroll
            for (int j = 0; j < 16; ++j) {
                float v1 = qv1 + acc0[j]; v1 = (v1 >= 0.f) ? v1 : NEG_SLOPE * v1;
                float v2 = qv2 + acc1[j]; v2 = (v2 >= 0.f) ? v2 : NEG_SLOPE * v2;
                sc[j] += v1 * wv1 + v2 * wv2;
            }
        }
    }

    // per-atom warp reduction of score partials (warp is unique writer)
    #pragma unroll
    for (int j = 0; j < 16; ++j) {
        float t = sc[j];
        #pragma unroll
        for (int off = 16; off; off >>= 1)
            t += __shfl_xor_sync(0xffffffffu, t, off);
        if (lane == 0 && a0 + j < nact) s_arr[a0 + j] = bal + t;
    }
    __syncthreads();

    // ---- softmax over active atoms (masked atoms are exactly 0 in ref) ----
    if (nact > 0) {
        float v = (tid < nact) ? s_arr[tid] : -INFINITY;
        float t = v;
        #pragma unroll
        for (int off = 16; off; off >>= 1)
            t = fmaxf(t, __shfl_xor_sync(0xffffffffu, t, off));
        if (lane == 0) red[wid] = t;
        __syncthreads();
        float mx = red[0];
        #pragma unroll
        for (int w = 1; w < 8; ++w) mx = fmaxf(mx, red[w]);
        __syncthreads();

        float p = (tid < nact) ? __expf(v - mx) : 0.f;
        float ts = p;
        #pragma unroll
        for (int off = 16; off; off >>= 1)
            ts += __shfl_xor_sync(0xffffffffu, ts, off);
        if (lane == 0) red[wid] = ts;
        __syncthreads();
        float Z = red[0];
        #pragma unroll
        for (int w = 1; w < 8; ++w) Z += red[w];
        if (tid < nact) p_arr[tid] = p / Z;
        __syncthreads();
    }

    // ---- y[k] = sum_a attn[a] * A[a,k] (4 independent chains) ----
    {
        float acc0 = 0.f, acc1 = 0.f, acc2 = 0.f, acc3 = 0.f;
        int a = 0;
        for (; a + 4 <= nact; a += 4) {
            acc0 += p_arr[a+0] * A_s[(long)(a+0) * DD + tid];
            acc1 += p_arr[a+1] * A_s[(long)(a+1) * DD + tid];
            acc2 += p_arr[a+2] * A_s[(long)(a+2) * DD + tid];
            acc3 += p_arr[a+3] * A_s[(long)(a+3) * DD + tid];
        }
        for (; a < nact; ++a)
            acc0 += p_arr[a] * A_s[(long)a * DD + tid];
        y_s[tid] = (acc0 + acc1) + (acc2 + acc3);
    }
    __syncthreads();

    // ---- ctx[d] = y @ W2.T + b2 ----
    {
        float acc = (nact > 0) ? b2[tid] : 0.f;
        const float4* w4 = (const float4*)(W2 + (long)tid * DD);
        #pragma unroll 8
        for (int k4 = 0; k4 < DD / 4; ++k4) {
            float4 wv = w4[k4];
            acc += y_s[4*k4+0]*wv.x + y_s[4*k4+1]*wv.y
                 + y_s[4*k4+2]*wv.z + y_s[4*k4+3]*wv.w;
        }
        ctx_s[tid] = acc;
    }
    __syncthreads();

    // ---- LayerNorm over D ----
    {
        float v = ctx_s[tid];
        float s1 = v;
        #pragma unroll
        for (int off = 16; off; off >>= 1)
            s1 += __shfl_xor_sync(0xffffffffu, s1, off);
        if (lane == 0) red[wid] = s1;
        __syncthreads();
        float total = red[0];
        #pragma unroll
        for (int w = 1; w < 8; ++w) total += red[w];
        const float mu = total * (1.f / DD);
        const float dv = v - mu;
        __syncthreads();

        float s2 = dv * dv;
        #pragma unroll
        for (int off = 16; off; off >>= 1)
            s2 += __shfl_xor_sync(0xffffffffu, s2, off);
        if (lane == 0) red[wid] = s2;
        __syncthreads();
        float tot2 = red[0];
        #pragma unroll
        for (int w = 1; w < 8; ++w) tot2 += red[w];
        const float var = tot2 * (1.f / DD);
        out[(long)b * DD + tid] = dv * rsqrtf(var + LN_EPS) * gamma_[tid] + beta_[tid];
    }
}

extern "C" void kernel_launch(void* const* d_in, const int* in_sizes, int n_in,
                              void* d_out, int out_size)
{
    const float* mol     = (const float*)d_in[0];
    const float* atom    = (const float*)d_in[1];
    const float* attend  = (const float*)d_in[2];
    const float* W1      = (const float*)d_in[4];
    const float* b1      = (const float*)d_in[5];
    const float* W2      = (const float*)d_in[6];
    const float* b2      = (const float*)d_in[7];
    const float* w_align = (const float*)d_in[8];
    const float* b_align = (const float*)d_in[9];
    const float* gamma_  = (const float*)d_in[10];
    const float* beta_   = (const float*)d_in[11];
    float* out = (float*)d_out;

    const int B = in_sizes[0] / DD;

    cudaFuncSetAttribute(gnn_agg_kernel,
                         cudaFuncAttributeMaxDynamicSharedMemorySize, SMEM_BYTES);
    gnn_agg_kernel<<<B, 256, SMEM_BYTES>>>(mol, atom, attend, W1, b1, W2, b2,
                                           w_align, b_align, gamma_, beta_, out);
}

// round 4
// speedup vs baseline: 1.6265x; 1.1107x over previous
#include <cuda_runtime.h>
#include <math.h>

#define DD 256
#define LL 128
#define NEG_SLOPE 0.2f
#define LN_EPS 1e-5f

// smem (floats): A_s 32768 | W2c 64*260=16640 | qb/w/x/y/ctx 5*256 | s_arr 128
//                p_arr 128 | red 32  (+ act[128] & cnts[8] ints)
static const int SMEM_FLOATS = 32768 + 16640 + 1280 + 128 + 128 + 32;
static const int SMEM_BYTES  = SMEM_FLOATS * 4 + (128 + 8) * 4;

__global__ __launch_bounds__(256, 1)
void gnn_agg_kernel(const float* __restrict__ mol,     // [B,D]
                    const float* __restrict__ atom,    // [B,L,D]
                    const float* __restrict__ attend,  // [B,L,1]
                    const float* __restrict__ W1,      // [D,D]
                    const float* __restrict__ b1,      // [D]
                    const float* __restrict__ W2,      // [D,D]
                    const float* __restrict__ b2,      // [D]
                    const float* __restrict__ w_align, // [D,1]
                    const float* __restrict__ b_align, // [1]
                    const float* __restrict__ gamma_,  // [D]
                    const float* __restrict__ beta_,   // [D]
                    float* __restrict__ out)           // [B,D]
{
    extern __shared__ float sm[];
    float* A_s   = sm;                      // compacted active atom rows
    float* W2c   = sm + 32768;              // [64][260] padded, natural rows
    float* qb_s  = W2c + 16640;             // q + b1 + b2
    float* w_s   = qb_s + DD;
    float* x_s   = w_s  + DD;
    float* y_s   = x_s  + DD;
    float* ctx_s = y_s  + DD;
    float* s_arr = ctx_s + DD;              // scores (accumulated per chunk)
    float* p_arr = s_arr + LL;
    float* red   = p_arr + LL;
    int*   act   = (int*)(red + 32);
    int*   cnts  = act + LL;

    const int b    = blockIdx.x;
    const int tid  = threadIdx.x;
    const int lane = tid & 31;
    const int wid  = tid >> 5;

    // ---- active-atom compaction ----
    int flag = 0;
    if (tid < LL) flag = (attend[(long)b * LL + tid] > 0.5f) ? 1 : 0;
    unsigned bm = __ballot_sync(0xffffffffu, flag);
    if (tid < LL && lane == 0) cnts[wid] = __popc(bm);
    __syncthreads();
    if (tid < LL && flag) {
        int base = 0;
        for (int w = 0; w < wid; ++w) base += cnts[w];
        act[base + __popc(bm & ((1u << lane) - 1u))] = tid;
    }
    if (tid == 0) cnts[4] = cnts[0] + cnts[1] + cnts[2] + cnts[3];

    x_s[tid] = mol[(long)b * DD + tid];
    w_s[tid] = w_align[tid];
    __syncthreads();
    const int nact = cnts[4];
    const float bal = b_align[0];

    // ---- load active atom rows into smem (float4, coalesced) ----
    {
        float4* A4w = (float4*)A_s;
        const float4* atom4 = (const float4*)atom;
        for (int idx = tid; idx < nact * 64; idx += 256) {
            int a = idx >> 6, k4 = idx & 63;
            A4w[idx] = atom4[((long)b * LL + act[a]) * 64 + k4];
        }
    }

    // ---- qb[d] = x @ W1.T + b1 + b2 ----
    {
        float acc = 0.f;
        const float4* w4 = (const float4*)(W1 + (long)tid * DD);
        #pragma unroll 8
        for (int k4 = 0; k4 < DD / 4; ++k4) {
            float4 wv = w4[k4];
            acc += x_s[4*k4+0]*wv.x + x_s[4*k4+1]*wv.y
                 + x_s[4*k4+2]*wv.z + x_s[4*k4+3]*wv.w;
        }
        qb_s[tid] = acc + b1[tid] + b2[tid];
    }

    // score accumulator init (consumed after next barrier)
    for (int a = tid; a < nact; a += 256) s_arr[a] = bal;

    // ---- score GEMM: balanced 64-atom tranches, 8 atoms x 2 d per thread ----
    const float4* A4 = (const float4*)A_s;

    for (int c = 0; c < 4; ++c) {
        __syncthreads();   // previous chunk's compute done before restage
        {
            const float4* Wg  = (const float4*)(W2 + (long)c * 64 * DD);
            float4*       Wc4 = (float4*)W2c;
            for (int idx = tid; idx < 64 * 64; idx += 256) {
                int r = idx >> 6, k4 = idx & 63;
                Wc4[r * 65 + k4] = Wg[r * 64 + k4];
            }
        }
        __syncthreads();

        const float qv1 = qb_s[c * 64 + lane];
        const float qv2 = qb_s[c * 64 + 32 + lane];
        const float wv1 = w_s[c * 64 + lane];
        const float wv2 = w_s[c * 64 + 32 + lane];
        const float4* Wr1 = (const float4*)W2c + lane * 65;
        const float4* Wr2 = (const float4*)W2c + (lane + 32) * 65;

        for (int t0 = 0; t0 < nact; t0 += 64) {
            const int abase = t0 + wid * 8;
            if (abase >= nact) continue;   // only final tranche is partial

            int roff[8];
            #pragma unroll
            for (int j = 0; j < 8; ++j)
                roff[j] = min(abase + j, nact - 1) * 64;

            float acc0[8], acc1[8];
            #pragma unroll
            for (int j = 0; j < 8; ++j) { acc0[j] = 0.f; acc1[j] = 0.f; }

            #pragma unroll 4
            for (int k4 = 0; k4 < 64; ++k4) {
                const float4 w1 = Wr1[k4];
                const float4 w2 = Wr2[k4];
                #pragma unroll
                for (int j = 0; j < 8; ++j) {
                    const float4 av = A4[roff[j] + k4];   // broadcast LDS.128
                    acc0[j] += av.x*w1.x + av.y*w1.y + av.z*w1.z + av.w*w1.w;
                    acc1[j] += av.x*w2.x + av.y*w2.y + av.z*w2.z + av.w*w2.w;
                }
            }
            #pragma unroll
            for (int j = 0; j < 8; ++j) {
                float v1 = qv1 + acc0[j]; v1 = (v1 >= 0.f) ? v1 : NEG_SLOPE * v1;
                float v2 = qv2 + acc1[j]; v2 = (v2 >= 0.f) ? v2 : NEG_SLOPE * v2;
                float contrib = v1 * wv1 + v2 * wv2;
                #pragma unroll
                for (int off = 16; off; off >>= 1)
                    contrib += __shfl_xor_sync(0xffffffffu, contrib, off);
                if (lane == 0 && abase + j < nact)
                    s_arr[abase + j] += contrib;   // unique writer warp per atom
            }
        }
    }
    __syncthreads();

    // ---- softmax over active atoms (masked atoms are exactly 0 in ref) ----
    if (nact > 0) {
        float v = (tid < nact) ? s_arr[tid] : -INFINITY;
        float t = v;
        #pragma unroll
        for (int off = 16; off; off >>= 1)
            t = fmaxf(t, __shfl_xor_sync(0xffffffffu, t, off));
        if (lane == 0) red[wid] = t;
        __syncthreads();
        float mx = red[0];
        #pragma unroll
        for (int w = 1; w < 8; ++w) mx = fmaxf(mx, red[w]);
        __syncthreads();

        float p = (tid < nact) ? __expf(v - mx) : 0.f;
        float ts = p;
        #pragma unroll
        for (int off = 16; off; off >>= 1)
            ts += __shfl_xor_sync(0xffffffffu, ts, off);
        if (lane == 0) red[wid] = ts;
        __syncthreads();
        float Z = red[0];
        #pragma unroll
        for (int w = 1; w < 8; ++w) Z += red[w];
        if (tid < nact) p_arr[tid] = p / Z;
        __syncthreads();
    }

    // ---- y[k] = sum_a attn[a] * A[a,k] (4 independent chains) ----
    {
        float acc0 = 0.f, acc1 = 0.f, acc2 = 0.f, acc3 = 0.f;
        int a = 0;
        for (; a + 4 <= nact; a += 4) {
            acc0 += p_arr[a+0] * A_s[(long)(a+0) * DD + tid];
            acc1 += p_arr[a+1] * A_s[(long)(a+1) * DD + tid];
            acc2 += p_arr[a+2] * A_s[(long)(a+2) * DD + tid];
            acc3 += p_arr[a+3] * A_s[(long)(a+3) * DD + tid];
        }
        for (; a < nact; ++a)
            acc0 += p_arr[a] * A_s[(long)a * DD + tid];
        y_s[tid] = (acc0 + acc1) + (acc2 + acc3);
    }
    __syncthreads();

    // ---- ctx[d] = y @ W2.T + b2 ----
    {
        float acc = (nact > 0) ? b2[tid] : 0.f;
        const float4* w4 = (const float4*)(W2 + (long)tid * DD);
        #pragma unroll 8
        for (int k4 = 0; k4 < DD / 4; ++k4) {
            float4 wv = w4[k4];
            acc += y_s[4*k4+0]*wv.x + y_s[4*k4+1]*wv.y
                 + y_s[4*k4+2]*wv.z + y_s[4*k4+3]*wv.w;
        }
        ctx_s[tid] = acc;
    }
    __syncthreads();

    // ---- LayerNorm over D ----
    {
        float v = ctx_s[tid];
        float s1 = v;
        #pragma unroll
        for (int off = 16; off; off >>= 1)
            s1 += __shfl_xor_sync(0xffffffffu, s1, off);
        if (lane == 0) red[wid] = s1;
        __syncthreads();
        float total = red[0];
        #pragma unroll
        for (int w = 1; w < 8; ++w) total += red[w];
        const float mu = total * (1.f / DD);
        const float dv = v - mu;
        __syncthreads();

        float s2 = dv * dv;
        #pragma unroll
        for (int off = 16; off; off >>= 1)
            s2 += __shfl_xor_sync(0xffffffffu, s2, off);
        if (lane == 0) red[wid] = s2;
        __syncthreads();
        float tot2 = red[0];
        #pragma unroll
        for (int w = 1; w < 8; ++w) tot2 += red[w];
        const float var = tot2 * (1.f / DD);
        out[(long)b * DD + tid] = dv * rsqrtf(var + LN_EPS) * gamma_[tid] + beta_[tid];
    }
}

extern "C" void kernel_launch(void* const* d_in, const int* in_sizes, int n_in,
                              void* d_out, int out_size)
{
    const float* mol     = (const float*)d_in[0];
    const float* atom    = (const float*)d_in[1];
    const float* attend  = (const float*)d_in[2];
    const float* W1      = (const float*)d_in[4];
    const float* b1      = (const float*)d_in[5];
    const float* W2      = (const float*)d_in[6];
    const float* b2      = (const float*)d_in[7];
    const float* w_align = (const float*)d_in[8];
    const float* b_align = (const float*)d_in[9];
    const float* gamma_  = (const float*)d_in[10];
    const float* beta_   = (const float*)d_in[11];
    float* out = (float*)d_out;

    const int B = in_sizes[0] / DD;

    cudaFuncSetAttribute(gnn_agg_kernel,
                         cudaFuncAttributeMaxDynamicSharedMemorySize, SMEM_BYTES);
    gnn_agg_kernel<<<B, 256, SMEM_BYTES>>>(mol, atom, attend, W1, b1, W2, b2,
                                           w_align, b_align, gamma_, beta_, out);
}

// round 5
// speedup vs baseline: 1.6663x; 1.0245x over previous
#include <cuda_runtime.h>
#include <math.h>

#define DD 256
#define LL 128
#define HALF 64
#define NEG_SLOPE 0.2f
#define LN_EPS 1e-5f

// smem (floats): A_s 64*256=16384 | W2c 128*260=33280 | qb/w/x/y/ctx 5*256=1280
//                s_arr 128 | p_arr 128 | red 32   (+ act[128] & cnts[8] ints)
static const int SMEM_FLOATS = 16384 + 33280 + 1280 + 128 + 128 + 32;
static const int SMEM_BYTES  = SMEM_FLOATS * 4 + (128 + 8) * 4;

__global__ __launch_bounds__(256, 1)
void gnn_agg_kernel(const float* __restrict__ mol,     // [B,D]
                    const float* __restrict__ atom,    // [B,L,D]
                    const float* __restrict__ attend,  // [B,L,1]
                    const float* __restrict__ W1,      // [D,D]
                    const float* __restrict__ b1,      // [D]
                    const float* __restrict__ W2,      // [D,D]
                    const float* __restrict__ b2,      // [D]
                    const float* __restrict__ w_align, // [D,1]
                    const float* __restrict__ b_align, // [1]
                    const float* __restrict__ gamma_,  // [D]
                    const float* __restrict__ beta_,   // [D]
                    float* __restrict__ out)           // [B,D]
{
    extern __shared__ float sm[];
    float* A_s   = sm;                      // one 64-atom half of active rows
    float* W2c   = sm + 16384;              // [128][260] padded (stride 65 f4)
    float* qb_s  = W2c + 33280;             // q + b1 + b2
    float* w_s   = qb_s + DD;
    float* x_s   = w_s  + DD;
    float* y_s   = x_s  + DD;               // y (half 0 accum / combined)
    float* ctx_s = y_s  + DD;               // y1 (half 1) then ctx
    float* s_arr = ctx_s + DD;              // raw scores, all active atoms
    float* p_arr = s_arr + LL;              // unnormalized exp weights (half)
    float* red   = p_arr + LL;              // red[0..7] warp partials,
                                            // red[16+h]=m_h, red[18+h]=Z_h
    int*   act   = (int*)(red + 32);
    int*   cnts  = act + LL;

    const int b    = blockIdx.x;
    const int tid  = threadIdx.x;
    const int lane = tid & 31;
    const int wid  = tid >> 5;

    // ---- active-atom compaction ----
    int flag = 0;
    if (tid < LL) flag = (attend[(long)b * LL + tid] > 0.5f) ? 1 : 0;
    unsigned bm = __ballot_sync(0xffffffffu, flag);
    if (tid < LL && lane == 0) cnts[wid] = __popc(bm);
    __syncthreads();
    if (tid < LL && flag) {
        int base = 0;
        for (int w = 0; w < wid; ++w) base += cnts[w];
        act[base + __popc(bm & ((1u << lane) - 1u))] = tid;
    }
    if (tid == 0) cnts[4] = cnts[0] + cnts[1] + cnts[2] + cnts[3];

    x_s[tid] = mol[(long)b * DD + tid];
    w_s[tid] = w_align[tid];
    __syncthreads();
    const int nact = cnts[4];
    const float bal = b_align[0];

    // ---- qb[d] = x @ W1.T + b1 + b2 ----
    {
        float acc = 0.f;
        const float4* w4 = (const float4*)(W1 + (long)tid * DD);
        #pragma unroll 8
        for (int k4 = 0; k4 < DD / 4; ++k4) {
            float4 wv = w4[k4];
            acc += x_s[4*k4+0]*wv.x + x_s[4*k4+1]*wv.y
                 + x_s[4*k4+2]*wv.z + x_s[4*k4+3]*wv.w;
        }
        qb_s[tid] = acc + b1[tid] + b2[tid];
    }
    for (int a = tid; a < nact; a += 256) s_arr[a] = bal;

    const float4* A4 = (const float4*)A_s;
    const int nhalves = (nact > HALF) ? 2 : (nact > 0 ? 1 : 0);

    for (int h = 0; h < nhalves; ++h) {
        const int nh = min(HALF, nact - h * HALF);
        float* yh = (h == 0) ? y_s : ctx_s;

        __syncthreads();   // previous half's y-accum done before A_s overwrite
        {   // load this half's atom rows (float4, coalesced)
            float4* A4w = (float4*)A_s;
            const float4* atom4 = (const float4*)atom;
            for (int idx = tid; idx < nh * 64; idx += 256) {
                int a = idx >> 6, k4 = idx & 63;
                A4w[idx] = atom4[((long)b * LL + act[h * HALF + a]) * 64 + k4];
            }
        }

        // ---- score GEMM over 2 W chunks of 128 d's ----
        for (int c = 0; c < 2; ++c) {
            __syncthreads();   // A_s ready (c==0) / previous chunk done
            {
                const float4* Wg  = (const float4*)(W2 + (long)c * 128 * DD);
                float4*       Wc4 = (float4*)W2c;
                for (int idx = tid; idx < 128 * 64; idx += 256) {
                    int r = idx >> 6, k4 = idx & 63;
                    Wc4[r * 65 + k4] = Wg[r * 64 + k4];
                }
            }
            __syncthreads();

            const int abase = wid * 8;       // local atom base within half
            if (abase < nh) {
                float qv[4], wv[4];
                const float4* Wr[4];
                #pragma unroll
                for (int m = 0; m < 4; ++m) {
                    const int dl = lane + 32 * m;
                    qv[m] = qb_s[c * 128 + dl];
                    wv[m] = w_s[c * 128 + dl];
                    Wr[m] = (const float4*)W2c + dl * 65;
                }
                int roff[8];
                #pragma unroll
                for (int j = 0; j < 8; ++j)
                    roff[j] = min(abase + j, nh - 1) * 64;

                float acc[8][4];
                #pragma unroll
                for (int j = 0; j < 8; ++j)
                    #pragma unroll
                    for (int m = 0; m < 4; ++m) acc[j][m] = 0.f;

                #pragma unroll 2
                for (int k4 = 0; k4 < 64; ++k4) {
                    float4 w[4];
                    #pragma unroll
                    for (int m = 0; m < 4; ++m) w[m] = Wr[m][k4];
                    #pragma unroll
                    for (int j = 0; j < 8; ++j) {
                        const float4 av = A4[roff[j] + k4];  // broadcast
                        #pragma unroll
                        for (int m = 0; m < 4; ++m)
                            acc[j][m] += av.x*w[m].x + av.y*w[m].y
                                       + av.z*w[m].z + av.w*w[m].w;
                    }
                }
                #pragma unroll
                for (int j = 0; j < 8; ++j) {
                    float contrib = 0.f;
                    #pragma unroll
                    for (int m = 0; m < 4; ++m) {
                        float v = qv[m] + acc[j][m];
                        v = (v >= 0.f) ? v : NEG_SLOPE * v;
                        contrib += v * wv[m];
                    }
                    #pragma unroll
                    for (int off = 16; off; off >>= 1)
                        contrib += __shfl_xor_sync(0xffffffffu, contrib, off);
                    if (lane == 0 && abase + j < nh)
                        s_arr[h * HALF + abase + j] += contrib; // unique writer
                }
            }
        }
        __syncthreads();

        // ---- half-local softmax numerator: m_h, Z_h, weights in p_arr ----
        {
            float v = (tid < nh) ? s_arr[h * HALF + tid] : -INFINITY;
            float t = v;
            #pragma unroll
            for (int off = 16; off; off >>= 1)
                t = fmaxf(t, __shfl_xor_sync(0xffffffffu, t, off));
            if (lane == 0) red[wid] = t;
            __syncthreads();
            float mh = red[0];
            #pragma unroll
            for (int w = 1; w < 8; ++w) mh = fmaxf(mh, red[w]);
            __syncthreads();

            float p = (tid < nh) ? __expf(v - mh) : 0.f;
            if (tid < nh) p_arr[tid] = p;
            float ts = p;
            #pragma unroll
            for (int off = 16; off; off >>= 1)
                ts += __shfl_xor_sync(0xffffffffu, ts, off);
            if (lane == 0) red[8 + wid] = ts;
            __syncthreads();
            if (tid == 0) {
                float Z = red[8];
                for (int w = 1; w < 8; ++w) Z += red[8 + w];
                red[16 + h] = mh;
                red[18 + h] = Z;
            }
            __syncthreads();
        }

        // ---- y_h[k] = sum_a p[a] * A[a,k] (unnormalized) ----
        {
            float acc0 = 0.f, acc1 = 0.f, acc2 = 0.f, acc3 = 0.f;
            int a = 0;
            for (; a + 4 <= nh; a += 4) {
                acc0 += p_arr[a+0] * A_s[(a+0) * DD + tid];
                acc1 += p_arr[a+1] * A_s[(a+1) * DD + tid];
                acc2 += p_arr[a+2] * A_s[(a+2) * DD + tid];
                acc3 += p_arr[a+3] * A_s[(a+3) * DD + tid];
            }
            for (; a < nh; ++a)
                acc0 += p_arr[a] * A_s[a * DD + tid];
            yh[tid] = (acc0 + acc1) + (acc2 + acc3);
        }
    }
    __syncthreads();

    // ---- combine halves: y = (y0*e^{m0-m} + y1*e^{m1-m}) / Z ----
    if (nhalves == 0) {
        y_s[tid] = 0.f;
    } else if (nhalves == 1) {
        y_s[tid] = y_s[tid] / red[18];
    } else {
        const float m0 = red[16], m1 = red[17];
        const float mx = fmaxf(m0, m1);
        const float sc0 = __expf(m0 - mx), sc1 = __expf(m1 - mx);
        const float Z = red[18] * sc0 + red[19] * sc1;
        y_s[tid] = (y_s[tid] * sc0 + ctx_s[tid] * sc1) / Z;
    }
    __syncthreads();

    // ---- ctx[d] = y @ W2.T + b2 ----
    {
        float acc = (nact > 0) ? b2[tid] : 0.f;
        const float4* w4 = (const float4*)(W2 + (long)tid * DD);
        #pragma unroll 8
        for (int k4 = 0; k4 < DD / 4; ++k4) {
            float4 wv = w4[k4];
            acc += y_s[4*k4+0]*wv.x + y_s[4*k4+1]*wv.y
                 + y_s[4*k4+2]*wv.z + y_s[4*k4+3]*wv.w;
        }
        ctx_s[tid] = acc;
    }
    __syncthreads();

    // ---- LayerNorm over D ----
    {
        float v = ctx_s[tid];
        float s1 = v;
        #pragma unroll
        for (int off = 16; off; off >>= 1)
            s1 += __shfl_xor_sync(0xffffffffu, s1, off);
        if (lane == 0) red[wid] = s1;
        __syncthreads();
        float total = red[0];
        #pragma unroll
        for (int w = 1; w < 8; ++w) total += red[w];
        const float mu = total * (1.f / DD);
        const float dv = v - mu;
        __syncthreads();

        float s2 = dv * dv;
        #pragma unroll
        for (int off = 16; off; off >>= 1)
            s2 += __shfl_xor_sync(0xffffffffu, s2, off);
        if (lane == 0) red[wid] = s2;
        __syncthreads();
        float tot2 = red[0];
        #pragma unroll
        for (int w = 1; w < 8; ++w) tot2 += red[w];
        const float var = tot2 * (1.f / DD);
        out[(long)b * DD + tid] = dv * rsqrtf(var + LN_EPS) * gamma_[tid] + beta_[tid];
    }
}

extern "C" void kernel_launch(void* const* d_in, const int* in_sizes, int n_in,
                              void* d_out, int out_size)
{
    const float* mol     = (const float*)d_in[0];
    const float* atom    = (const float*)d_in[1];
    const float* attend  = (const float*)d_in[2];
    const float* W1      = (const float*)d_in[4];
    const float* b1      = (const float*)d_in[5];
    const float* W2      = (const float*)d_in[6];
    const float* b2      = (const float*)d_in[7];
    const float* w_align = (const float*)d_in[8];
    const float* b_align = (const float*)d_in[9];
    const float* gamma_  = (const float*)d_in[10];
    const float* beta_   = (const float*)d_in[11];
    float* out = (float*)d_out;

    const int B = in_sizes[0] / DD;

    cudaFuncSetAttribute(gnn_agg_kernel,
                         cudaFuncAttributeMaxDynamicSharedMemorySize, SMEM_BYTES);
    gnn_agg_kernel<<<B, 256, SMEM_BYTES>>>(mol, atom, attend, W1, b1, W2, b2,
                                           w_align, b_align, gamma_, beta_, out);
}

// round 8
// speedup vs baseline: 2.0453x; 1.2274x over previous
#include <cuda_runtime.h>
#include <cuda_bf16.h>
#include <math.h>
#include <stdint.h>

#define DD 256
#define LL 128
#define NEG_SLOPE 0.2f
#define LN_EPS 1e-5f
#define KSTR 264            // smem row stride in bf16 halves (conflict-free)

// smem byte offsets
#define A_HI 0                              // [128][264] bf16 = 67584 B
#define A_LO 67584
#define W_HI 135168                         // [64][264] bf16 = 33792 B
#define W_LO 168960
#define MISC 202752                         // floats
static const int SMEM_BYTES = MISC + 1568 * 4;   // 209024

static __device__ __forceinline__ uint32_t smem_u32(const void* p) {
    uint32_t a;
    asm("{ .reg .u64 t; cvta.to.shared.u64 t, %1; cvt.u32.u64 %0, t; }"
        : "=r"(a) : "l"(p));
    return a;
}

#define LDSM_X4(r0, r1, r2, r3, addr) \
    asm volatile("ldmatrix.sync.aligned.m8n8.x4.shared.b16 {%0,%1,%2,%3}, [%4];" \
        : "=r"(r0), "=r"(r1), "=r"(r2), "=r"(r3) : "r"(addr))
#define MMA_BF16(c, a, b0, b1) \
    asm volatile("mma.sync.aligned.m16n8k16.row.col.f32.bf16.bf16.f32 " \
        "{%0,%1,%2,%3}, {%4,%5,%6,%7}, {%8,%9}, {%0,%1,%2,%3};" \
        : "+f"((c)[0]), "+f"((c)[1]), "+f"((c)[2]), "+f"((c)[3]) \
        : "r"((a)[0]), "r"((a)[1]), "r"((a)[2]), "r"((a)[3]), "r"(b0), "r"(b1))

__global__ __launch_bounds__(256, 1)
void gnn_agg_kernel(const float* __restrict__ mol,     // [B,D]
                    const float* __restrict__ atom,    // [B,L,D]
                    const float* __restrict__ attend,  // [B,L,1]
                    const float* __restrict__ smask,   // [B,L,1]
                    const float* __restrict__ W1,      // [D,D]
                    const float* __restrict__ b1,      // [D]
                    const float* __restrict__ W2,      // [D,D]
                    const float* __restrict__ b2,      // [D]
                    const float* __restrict__ w_align, // [D,1]
                    const float* __restrict__ b_align, // [1]
                    const float* __restrict__ gamma_,  // [D]
                    const float* __restrict__ beta_,   // [D]
                    float* __restrict__ out)           // [B,D]
{
    extern __shared__ char smem[];
    const uint32_t smb = smem_u32(smem);
    float* qb_s  = (float*)(smem + MISC);
    float* w_s   = qb_s + 256;
    float* x_s   = w_s  + 256;
    float* y_s   = x_s  + 256;
    float* ctx_s = y_s  + 256;
    float* s_arr = ctx_s + 256;   // 128
    float* p_arr = s_arr + 128;   // 128
    float* red   = p_arr + 128;   // 32

    const int b    = blockIdx.x;
    const int tid  = threadIdx.x;
    const int lane = tid & 31;
    const int wid  = tid >> 5;

    x_s[tid] = mol[(long)b * DD + tid];
    w_s[tid] = w_align[tid];
    __syncthreads();
    const float bal = b_align[0];

    // ---- qb[d] = mol @ W1.T + b1 + b2 ----
    {
        float acc = 0.f;
        const float4* w4 = (const float4*)(W1 + (long)tid * DD);
        #pragma unroll 8
        for (int k4 = 0; k4 < DD / 4; ++k4) {
            float4 wv = w4[k4];
            acc += x_s[4*k4+0]*wv.x + x_s[4*k4+1]*wv.y
                 + x_s[4*k4+2]*wv.z + x_s[4*k4+3]*wv.w;
        }
        qb_s[tid] = acc + b1[tid] + b2[tid];
    }

    // ---- stage A = atom[b] as bf16 hi/lo, padded rows ----
    for (int idx = tid; idx < LL * (DD / 2); idx += 256) {
        const int r  = idx >> 7;          // atom row
        const int kp = idx & 127;         // float2 index along k
        const float2 v = ((const float2*)(atom + ((long)b * LL + r) * DD))[kp];
        __nv_bfloat16 hx = __float2bfloat16(v.x);
        __nv_bfloat16 hy = __float2bfloat16(v.y);
        __nv_bfloat16 lx = __float2bfloat16(v.x - __bfloat162float(hx));
        __nv_bfloat16 ly = __float2bfloat16(v.y - __bfloat162float(hy));
        const int off = (r * KSTR + kp * 2) * 2;
        __nv_bfloat162 h; h.x = hx; h.y = hy;
        __nv_bfloat162 l; l.x = lx; l.y = ly;
        *(__nv_bfloat162*)(smem + A_HI + off) = h;
        *(__nv_bfloat162*)(smem + A_LO + off) = l;
    }

    // per-lane ldmatrix base addresses
    const uint32_t aRow  = 16 * wid + (lane & 15);
    const uint32_t aColh = (lane >> 4) << 3;
    const uint32_t aOff  = (aRow * KSTR + aColh) * 2;
    const uint32_t addrAhi = smb + A_HI + aOff;
    const uint32_t addrAlo = smb + A_LO + aOff;
    // B (non-trans): lanes 0-7: n0-7/k0-7, 8-15: n0-7/k8-15,
    //                16-23: n8-15/k0-7, 24-31: n8-15/k8-15
    const uint32_t bRow  = ((lane >> 4) << 3) + (lane & 7);
    const uint32_t bColh = ((lane >> 3) & 1) << 3;
    const uint32_t bOff  = (bRow * KSTR + bColh) * 2;

    float sc0 = 0.f, sc1 = 0.f;   // score partials for rows 16w+lane/4, +8

    for (int nc = 0; nc < 4; ++nc) {
        __syncthreads();   // A ready (nc==0) / prior chunk compute done
        // stage W2 rows [nc*64, nc*64+64) as bf16 hi/lo
        for (int idx = tid; idx < 64 * (DD / 2); idx += 256) {
            const int r  = idx >> 7;
            const int kp = idx & 127;
            const float2 v = ((const float2*)(W2 + (long)(nc * 64 + r) * DD))[kp];
            __nv_bfloat16 hx = __float2bfloat16(v.x);
            __nv_bfloat16 hy = __float2bfloat16(v.y);
            __nv_bfloat16 lx = __float2bfloat16(v.x - __bfloat162float(hx));
            __nv_bfloat16 ly = __float2bfloat16(v.y - __bfloat162float(hy));
            const int off = (r * KSTR + kp * 2) * 2;
            __nv_bfloat162 h; h.x = hx; h.y = hy;
            __nv_bfloat162 l; l.x = lx; l.y = ly;
            *(__nv_bfloat162*)(smem + W_HI + off) = h;
            *(__nv_bfloat162*)(smem + W_LO + off) = l;
        }
        __syncthreads();

        float acc[8][4];
        #pragma unroll
        for (int nt = 0; nt < 8; ++nt)
            #pragma unroll
            for (int q = 0; q < 4; ++q) acc[nt][q] = 0.f;

        #pragma unroll 2
        for (int ks = 0; ks < 16; ++ks) {
            uint32_t ah[4], al[4];
            LDSM_X4(ah[0], ah[1], ah[2], ah[3], addrAhi + ks * 32);
            LDSM_X4(al[0], al[1], al[2], al[3], addrAlo + ks * 32);
            #pragma unroll
            for (int ntp = 0; ntp < 4; ++ntp) {
                const uint32_t bo = bOff + ntp * (16 * KSTR * 2) + ks * 32;
                uint32_t bh[4], bl[4];
                LDSM_X4(bh[0], bh[1], bh[2], bh[3], smb + W_HI + bo);
                LDSM_X4(bl[0], bl[1], bl[2], bl[3], smb + W_LO + bo);
                MMA_BF16(acc[2*ntp+0], ah, bh[0], bh[1]);
                MMA_BF16(acc[2*ntp+0], al, bh[0], bh[1]);
                MMA_BF16(acc[2*ntp+0], ah, bl[0], bl[1]);
                MMA_BF16(acc[2*ntp+1], ah, bh[2], bh[3]);
                MMA_BF16(acc[2*ntp+1], al, bh[2], bh[3]);
                MMA_BF16(acc[2*ntp+1], ah, bl[2], bl[3]);
            }
        }

        // epilogue: fold leakyrelu(qb + S) * w_align into per-row partials
        #pragma unroll
        for (int nt = 0; nt < 8; ++nt) {
            const int c = nc * 64 + nt * 8 + (lane & 3) * 2;
            const float q0 = qb_s[c], q1 = qb_s[c + 1];
            const float w0 = w_s[c],  w1 = w_s[c + 1];
            float v;
            v = q0 + acc[nt][0]; v = (v >= 0.f) ? v : NEG_SLOPE * v; sc0 += v * w0;
            v = q1 + acc[nt][1]; v = (v >= 0.f) ? v : NEG_SLOPE * v; sc0 += v * w1;
            v = q0 + acc[nt][2]; v = (v >= 0.f) ? v : NEG_SLOPE * v; sc1 += v * w0;
            v = q1 + acc[nt][3]; v = (v >= 0.f) ? v : NEG_SLOPE * v; sc1 += v * w1;
        }
    }

    // quad-reduce score partials; lane%4==0 writes rows 16w+lane/4 (+8)
    sc0 += __shfl_xor_sync(0xffffffffu, sc0, 1);
    sc0 += __shfl_xor_sync(0xffffffffu, sc0, 2);
    sc1 += __shfl_xor_sync(0xffffffffu, sc1, 1);
    sc1 += __shfl_xor_sync(0xffffffffu, sc1, 2);
    if ((lane & 3) == 0) {
        const int r0 = 16 * wid + (lane >> 2);
        s_arr[r0]     = bal + sc0 + smask[(long)b * LL + r0];
        s_arr[r0 + 8] = bal + sc1 + smask[(long)b * LL + r0 + 8];
    }
    __syncthreads();

    // ---- softmax over 128 atoms (masked exps underflow to exactly 0) ----
    {
        float v = (tid < LL) ? s_arr[tid] : -INFINITY;
        float t = v;
        #pragma unroll
        for (int off = 16; off; off >>= 1)
            t = fmaxf(t, __shfl_xor_sync(0xffffffffu, t, off));
        if (lane == 0) red[wid] = t;
        __syncthreads();
        float mx = red[0];
        #pragma unroll
        for (int w = 1; w < 8; ++w) mx = fmaxf(mx, red[w]);
        __syncthreads();

        float e = (tid < LL) ? __expf(v - mx) : 0.f;
        float ts = e;
        #pragma unroll
        for (int off = 16; off; off >>= 1)
            ts += __shfl_xor_sync(0xffffffffu, ts, off);
        if (lane == 0) red[wid] = ts;
        __syncthreads();
        float Z = red[0];
        #pragma unroll
        for (int w = 1; w < 8; ++w) Z += red[w];

        float att = (tid < LL) ? attend[(long)b * LL + tid] : 0.f;
        float pf = e * att / Z;
        if (tid < LL) p_arr[tid] = pf;
        float tc = pf;
        #pragma unroll
        for (int off = 16; off; off >>= 1)
            tc += __shfl_xor_sync(0xffffffffu, tc, off);
        if (lane == 0) red[8 + wid] = tc;
        __syncthreads();
        if (tid == 0) {
            float cb = red[8];
            for (int w = 1; w < 8; ++w) cb += red[8 + w];
            red[30] = cb;                 // sum of attn (b2 coefficient)
        }
        __syncthreads();
    }

    // ---- y[k] = sum_a attn[a] * atom[a,k] (gmem rows, L2-hot) ----
    {
        const float* Ab = atom + (long)b * LL * DD;
        float acc0 = 0.f, acc1 = 0.f;
        #pragma unroll 2
        for (int a = 0; a < LL; a += 2) {
            const float p0 = p_arr[a], p1 = p_arr[a + 1];
            if (p0 != 0.f) acc0 += p0 * Ab[(long)a * DD + tid];
            if (p1 != 0.f) acc1 += p1 * Ab[(long)(a + 1) * DD + tid];
        }
        y_s[tid] = acc0 + acc1;
    }
    __syncthreads();

    // ---- ctx[d] = y @ W2.T + (sum attn)*b2 ----
    {
        float acc = red[30] * b2[tid];
        const float4* w4 = (const float4*)(W2 + (long)tid * DD);
        #pragma unroll 8
        for (int k4 = 0; k4 < DD / 4; ++k4) {
            float4 wv = w4[k4];
            acc += y_s[4*k4+0]*wv.x + y_s[4*k4+1]*wv.y
                 + y_s[4*k4+2]*wv.z + y_s[4*k4+3]*wv.w;
        }
        ctx_s[tid] = acc;
    }
    __syncthreads();

    // ---- LayerNorm over D ----
    {
        float v = ctx_s[tid];
        float s1 = v;
        #pragma unroll
        for (int off = 16; off; off >>= 1)
            s1 += __shfl_xor_sync(0xffffffffu, s1, off);
        if (lane == 0) red[wid] = s1;
        __syncthreads();
        float total = red[0];
        #pragma unroll
        for (int w = 1; w < 8; ++w) total += red[w];
        const float mu = total * (1.f / DD);
        const float dv = v - mu;
        __syncthreads();

        float s2 = dv * dv;
        #pragma unroll
        for (int off = 16; off; off >>= 1)
            s2 += __shfl_xor_sync(0xffffffffu, s2, off);
        if (lane == 0) red[wid] = s2;
        __syncthreads();
        float tot2 = red[0];
        #pragma unroll
        for (int w = 1; w < 8; ++w) tot2 += red[w];
        const float var = tot2 * (1.f / DD);
        out[(long)b * DD + tid] = dv * rsqrtf(var + LN_EPS) * gamma_[tid] + beta_[tid];
    }
}

extern "C" void kernel_launch(void* const* d_in, const int* in_sizes, int n_in,
                              void* d_out, int out_size)
{
    const float* mol     = (const float*)d_in[0];
    const float* atom    = (const float*)d_in[1];
    const float* attend  = (const float*)d_in[2];
    const float* smask   = (const float*)d_in[3];
    const float* W1      = (const float*)d_in[4];
    const float* b1      = (const float*)d_in[5];
    const float* W2      = (const float*)d_in[6];
    const float* b2      = (const float*)d_in[7];
    const float* w_align = (const float*)d_in[8];
    const float* b_align = (const float*)d_in[9];
    const float* gamma_  = (const float*)d_in[10];
    const float* beta_   = (const float*)d_in[11];
    float* out = (float*)d_out;

    const int B = in_sizes[0] / DD;

    cudaFuncSetAttribute(gnn_agg_kernel,
                         cudaFuncAttributeMaxDynamicSharedMemorySize, SMEM_BYTES);
    gnn_agg_kernel<<<B, 256, SMEM_BYTES>>>(mol, atom, attend, smask, W1, b1, W2, b2,
                                           w_align, b_align, gamma_, beta_, out);
}

// round 9
// speedup vs baseline: 2.2518x; 1.1010x over previous
#include <cuda_runtime.h>
#include <cuda_bf16.h>
#include <math.h>
#include <stdint.h>

#define DD 256
#define LL 128
#define NEG_SLOPE 0.2f
#define LN_EPS 1e-5f
#define KSTR 264            // smem row stride in bf16 halves (conflict-free)

// smem byte offsets
#define A_HI 0                              // [128][264] bf16 = 67584 B
#define A_LO 67584
#define W_HI 135168                         // [64][264] bf16 = 33792 B
#define W_LO 168960
#define MISC 202752                         // floats
// misc floats: qb 0, w 256, x 512, y 768, ctx 1024, s_part 1280(2*128), p 1536, red 1664
static const int SMEM_BYTES = MISC + 1696 * 4;   // 209536

// precomputed W2 bf16 hi/lo, exact smem image (row-major, KSTR stride, pads 0)
__device__ __align__(16) __nv_bfloat16 g_Whi[256 * KSTR];
__device__ __align__(16) __nv_bfloat16 g_Wlo[256 * KSTR];

__global__ void prep_w2(const float* __restrict__ W2) {
    const int r = blockIdx.x;            // 0..255 output dim
    for (int k = threadIdx.x; k < KSTR; k += blockDim.x) {
        float v = (k < DD) ? W2[(long)r * DD + k] : 0.f;
        __nv_bfloat16 h = __float2bfloat16(v);
        __nv_bfloat16 l = __float2bfloat16(v - __bfloat162float(h));
        g_Whi[(long)r * KSTR + k] = h;
        g_Wlo[(long)r * KSTR + k] = l;
    }
}

static __device__ __forceinline__ uint32_t smem_u32(const void* p) {
    uint32_t a;
    asm("{ .reg .u64 t; cvta.to.shared.u64 t, %1; cvt.u32.u64 %0, t; }"
        : "=r"(a) : "l"(p));
    return a;
}

#define LDSM_X4(r0, r1, r2, r3, addr) \
    asm volatile("ldmatrix.sync.aligned.m8n8.x4.shared.b16 {%0,%1,%2,%3}, [%4];" \
        : "=r"(r0), "=r"(r1), "=r"(r2), "=r"(r3) : "r"(addr))
#define MMA_BF16(c, a, b0, b1) \
    asm volatile("mma.sync.aligned.m16n8k16.row.col.f32.bf16.bf16.f32 " \
        "{%0,%1,%2,%3}, {%4,%5,%6,%7}, {%8,%9}, {%0,%1,%2,%3};" \
        : "+f"((c)[0]), "+f"((c)[1]), "+f"((c)[2]), "+f"((c)[3]) \
        : "r"((a)[0]), "r"((a)[1]), "r"((a)[2]), "r"((a)[3]), "r"(b0), "r"(b1))

__global__ __launch_bounds__(256, 1)
void gnn_agg_kernel(const float* __restrict__ mol,     // [B,D]
                    const float* __restrict__ atom,    // [B,L,D]
                    const float* __restrict__ attend,  // [B,L,1]
                    const float* __restrict__ smask,   // [B,L,1]
                    const float* __restrict__ W1,      // [D,D]
                    const float* __restrict__ b1,      // [D]
                    const float* __restrict__ W2,      // [D,D]
                    const float* __restrict__ b2,      // [D]
                    const float* __restrict__ w_align, // [D,1]
                    const float* __restrict__ b_align, // [1]
                    const float* __restrict__ gamma_,  // [D]
                    const float* __restrict__ beta_,   // [D]
                    float* __restrict__ out)           // [B,D]
{
    extern __shared__ char smem[];
    const uint32_t smb = smem_u32(smem);
    float* qb_s   = (float*)(smem + MISC);
    float* w_s    = qb_s + 256;
    float* x_s    = w_s  + 256;
    float* y_s    = x_s  + 256;
    float* ctx_s  = y_s  + 256;
    float* s_part = ctx_s + 256;  // [2][128]
    float* p_arr  = s_part + 256; // 128
    float* red    = p_arr + 128;  // 32

    const int b    = blockIdx.x;
    const int tid  = threadIdx.x;
    const int lane = tid & 31;
    const int wid  = tid >> 5;
    const int mq   = wid >> 1;    // atom-quarter: rows [32mq, 32mq+32)
    const int nh   = wid & 1;     // n-half of 64-d chunk

    x_s[tid] = mol[(long)b * DD + tid];
    w_s[tid] = w_align[tid];
    __syncthreads();
    const float bal = b_align[0];

    // ---- qb[d] = mol @ W1.T + b1 + b2 ----
    {
        float acc = 0.f;
        const float4* w4 = (const float4*)(W1 + (long)tid * DD);
        #pragma unroll 8
        for (int k4 = 0; k4 < DD / 4; ++k4) {
            float4 wv = w4[k4];
            acc += x_s[4*k4+0]*wv.x + x_s[4*k4+1]*wv.y
                 + x_s[4*k4+2]*wv.z + x_s[4*k4+3]*wv.w;
        }
        qb_s[tid] = acc + b1[tid] + b2[tid];
    }

    // ---- stage A = atom[b] as bf16 hi/lo, padded rows ----
    for (int idx = tid; idx < LL * (DD / 2); idx += 256) {
        const int r  = idx >> 7;
        const int kp = idx & 127;
        const float2 v = ((const float2*)(atom + ((long)b * LL + r) * DD))[kp];
        __nv_bfloat16 hx = __float2bfloat16(v.x);
        __nv_bfloat16 hy = __float2bfloat16(v.y);
        __nv_bfloat16 lx = __float2bfloat16(v.x - __bfloat162float(hx));
        __nv_bfloat16 ly = __float2bfloat16(v.y - __bfloat162float(hy));
        const int off = (r * KSTR + kp * 2) * 2;
        __nv_bfloat162 h; h.x = hx; h.y = hy;
        __nv_bfloat162 l; l.x = lx; l.y = ly;
        *(__nv_bfloat162*)(smem + A_HI + off) = h;
        *(__nv_bfloat162*)(smem + A_LO + off) = l;
    }

    // fragment base addresses (validated mappings from round 8)
    uint32_t addrAh[2], addrAl[2], addrBh[2], addrBl[2];
    {
        const uint32_t aColh = (lane >> 4) << 3;
        #pragma unroll
        for (int mt = 0; mt < 2; ++mt) {
            const uint32_t off = (((uint32_t)(32 * mq + 16 * mt) + (lane & 15)) * KSTR + aColh) * 2;
            addrAh[mt] = smb + A_HI + off;
            addrAl[mt] = smb + A_LO + off;
        }
        const uint32_t bIn16 = ((lane >> 4) << 3) + (lane & 7);
        const uint32_t bColh = ((lane >> 3) & 1) << 3;
        #pragma unroll
        for (int nt = 0; nt < 2; ++nt) {
            const uint32_t off = (((uint32_t)(32 * nh + 16 * nt) + bIn16) * KSTR + bColh) * 2;
            addrBh[nt] = smb + W_HI + off;
            addrBl[nt] = smb + W_LO + off;
        }
    }

    float sc[2][2] = {{0.f, 0.f}, {0.f, 0.f}};   // [mt][rowhalf]

    #pragma unroll 1
    for (int nc = 0; nc < 4; ++nc) {
        __syncthreads();   // A ready (nc==0) / prior chunk compute done
        // copy precomputed W chunk hi/lo (no conversion math)
        {
            const uint4* sh = (const uint4*)(g_Whi + (long)nc * 64 * KSTR);
            const uint4* sl = (const uint4*)(g_Wlo + (long)nc * 64 * KSTR);
            uint4* dh = (uint4*)(smem + W_HI);
            uint4* dl = (uint4*)(smem + W_LO);
            #pragma unroll
            for (int i = 0; i < 9; ++i) {          // 9*256 >= 2112
                const int idx = i * 256 + tid;
                if (idx < 2112) { dh[idx] = sh[idx]; dl[idx] = sl[idx]; }
            }
        }
        __syncthreads();

        float acc[2][4][4];
        #pragma unroll
        for (int mt = 0; mt < 2; ++mt)
            #pragma unroll
            for (int j = 0; j < 4; ++j)
                #pragma unroll
                for (int q = 0; q < 4; ++q) acc[mt][j][q] = 0.f;

        uint32_t fAh[2][2][4], fAl[2][2][4], fBh[2][2][4], fBl[2][2][4];

        #define LOADF(buf, ks) do {                                              \
            const uint32_t ko = (uint32_t)(ks) * 32;                             \
            LDSM_X4(fAh[buf][0][0], fAh[buf][0][1], fAh[buf][0][2], fAh[buf][0][3], addrAh[0] + ko); \
            LDSM_X4(fAh[buf][1][0], fAh[buf][1][1], fAh[buf][1][2], fAh[buf][1][3], addrAh[1] + ko); \
            LDSM_X4(fAl[buf][0][0], fAl[buf][0][1], fAl[buf][0][2], fAl[buf][0][3], addrAl[0] + ko); \
            LDSM_X4(fAl[buf][1][0], fAl[buf][1][1], fAl[buf][1][2], fAl[buf][1][3], addrAl[1] + ko); \
            LDSM_X4(fBh[buf][0][0], fBh[buf][0][1], fBh[buf][0][2], fBh[buf][0][3], addrBh[0] + ko); \
            LDSM_X4(fBh[buf][1][0], fBh[buf][1][1], fBh[buf][1][2], fBh[buf][1][3], addrBh[1] + ko); \
            LDSM_X4(fBl[buf][0][0], fBl[buf][0][1], fBl[buf][0][2], fBl[buf][0][3], addrBl[0] + ko); \
            LDSM_X4(fBl[buf][1][0], fBl[buf][1][1], fBl[buf][1][2], fBl[buf][1][3], addrBl[1] + ko); \
        } while (0)

        LOADF(0, 0);
        #pragma unroll
        for (int ks = 0; ks < 16; ++ks) {
            const int cur = ks & 1;
            if (ks < 15) LOADF(cur ^ 1, ks + 1);
            #pragma unroll
            for (int mt = 0; mt < 2; ++mt)
                #pragma unroll
                for (int nt = 0; nt < 2; ++nt) {
                    float* A0 = acc[mt][2 * nt + 0];
                    float* A1 = acc[mt][2 * nt + 1];
                    MMA_BF16(A0, fAh[cur][mt], fBh[cur][nt][0], fBh[cur][nt][1]);
                    MMA_BF16(A0, fAl[cur][mt], fBh[cur][nt][0], fBh[cur][nt][1]);
                    MMA_BF16(A0, fAh[cur][mt], fBl[cur][nt][0], fBl[cur][nt][1]);
                    MMA_BF16(A1, fAh[cur][mt], fBh[cur][nt][2], fBh[cur][nt][3]);
                    MMA_BF16(A1, fAl[cur][mt], fBh[cur][nt][2], fBh[cur][nt][3]);
                    MMA_BF16(A1, fAh[cur][mt], fBl[cur][nt][2], fBl[cur][nt][3]);
                }
        }
        #undef LOADF

        // epilogue: fold leakyrelu(qb + S) * w_align into per-row partials
        // acc[mt][j][q]: col = nc*64 + nh*32 + (j>>1)*16 + (j&1)*8 + (lane&3)*2 + (q&1)
        //                row = 32mq + 16mt + (lane>>2) + 8*(q>>1)
        #pragma unroll
        for (int mt = 0; mt < 2; ++mt)
            #pragma unroll
            for (int j = 0; j < 4; ++j) {
                const int c = nc * 64 + nh * 32 + (j >> 1) * 16 + (j & 1) * 8 + (lane & 3) * 2;
                const float q0 = qb_s[c], q1 = qb_s[c + 1];
                const float w0 = w_s[c],  w1 = w_s[c + 1];
                float v;
                v = q0 + acc[mt][j][0]; v = (v >= 0.f) ? v : NEG_SLOPE * v; sc[mt][0] += v * w0;
                v = q1 + acc[mt][j][1]; v = (v >= 0.f) ? v : NEG_SLOPE * v; sc[mt][0] += v * w1;
                v = q0 + acc[mt][j][2]; v = (v >= 0.f) ? v : NEG_SLOPE * v; sc[mt][1] += v * w0;
                v = q1 + acc[mt][j][3]; v = (v >= 0.f) ? v : NEG_SLOPE * v; sc[mt][1] += v * w1;
            }
    }

    // quad-reduce score partials; unique (nh, row) writer
    #pragma unroll
    for (int mt = 0; mt < 2; ++mt)
        #pragma unroll
        for (int rh = 0; rh < 2; ++rh) {
            float t = sc[mt][rh];
            t += __shfl_xor_sync(0xffffffffu, t, 1);
            t += __shfl_xor_sync(0xffffffffu, t, 2);
            if ((lane & 3) == 0)
                s_part[nh * LL + 32 * mq + 16 * mt + (lane >> 2) + 8 * rh] = t;
        }
    __syncthreads();

    // ---- softmax over 128 atoms (masked exps underflow to exactly 0) ----
    {
        float v = (tid < LL)
                ? (bal + s_part[tid] + s_part[LL + tid] + smask[(long)b * LL + tid])
                : -INFINITY;
        float t = v;
        #pragma unroll
        for (int off = 16; off; off >>= 1)
            t = fmaxf(t, __shfl_xor_sync(0xffffffffu, t, off));
        if (lane == 0) red[wid] = t;
        __syncthreads();
        float mx = red[0];
        #pragma unroll
        for (int w = 1; w < 8; ++w) mx = fmaxf(mx, red[w]);
        __syncthreads();

        float e = (tid < LL) ? __expf(v - mx) : 0.f;
        float ts = e;
        #pragma unroll
        for (int off = 16; off; off >>= 1)
            ts += __shfl_xor_sync(0xffffffffu, ts, off);
        if (lane == 0) red[wid] = ts;
        __syncthreads();
        float Z = red[0];
        #pragma unroll
        for (int w = 1; w < 8; ++w) Z += red[w];

        float att = (tid < LL) ? attend[(long)b * LL + tid] : 0.f;
        float pf = e * att / Z;
        if (tid < LL) p_arr[tid] = pf;
        float tc = pf;
        #pragma unroll
        for (int off = 16; off; off >>= 1)
            tc += __shfl_xor_sync(0xffffffffu, tc, off);
        if (lane == 0) red[8 + wid] = tc;
        __syncthreads();
        if (tid == 0) {
            float cb = red[8];
            for (int w = 1; w < 8; ++w) cb += red[8 + w];
            red[30] = cb;                 // sum of attn (b2 coefficient)
        }
        __syncthreads();
    }

    // ---- y[k] = sum_a attn[a] * atom[a,k] (gmem rows, L2-hot) ----
    {
        const float* Ab = atom + (long)b * LL * DD;
        float acc0 = 0.f, acc1 = 0.f;
        #pragma unroll 2
        for (int a = 0; a < LL; a += 2) {
            const float p0 = p_arr[a], p1 = p_arr[a + 1];
            if (p0 != 0.f) acc0 += p0 * Ab[(long)a * DD + tid];
            if (p1 != 0.f) acc1 += p1 * Ab[(long)(a + 1) * DD + tid];
        }
        y_s[tid] = acc0 + acc1;
    }
    __syncthreads();

    // ---- ctx[d] = y @ W2.T + (sum attn)*b2 ----
    {
        float acc = red[30] * b2[tid];
        const float4* w4 = (const float4*)(W2 + (long)tid * DD);
        #pragma unroll 8
        for (int k4 = 0; k4 < DD / 4; ++k4) {
            float4 wv = w4[k4];
            acc += y_s[4*k4+0]*wv.x + y_s[4*k4+1]*wv.y
                 + y_s[4*k4+2]*wv.z + y_s[4*k4+3]*wv.w;
        }
        ctx_s[tid] = acc;
    }
    __syncthreads();

    // ---- LayerNorm over D ----
    {
        float v = ctx_s[tid];
        float s1 = v;
        #pragma unroll
        for (int off = 16; off; off >>= 1)
            s1 += __shfl_xor_sync(0xffffffffu, s1, off);
        if (lane == 0) red[wid] = s1;
        __syncthreads();
        float total = red[0];
        #pragma unroll
        for (int w = 1; w < 8; ++w) total += red[w];
        const float mu = total * (1.f / DD);
        const float dv = v - mu;
        __syncthreads();

        float s2 = dv * dv;
        #pragma unroll
        for (int off = 16; off; off >>= 1)
            s2 += __shfl_xor_sync(0xffffffffu, s2, off);
        if (lane == 0) red[wid] = s2;
        __syncthreads();
        float tot2 = red[0];
        #pragma unroll
        for (int w = 1; w < 8; ++w) tot2 += red[w];
        const float var = tot2 * (1.f / DD);
        out[(long)b * DD + tid] = dv * rsqrtf(var + LN_EPS) * gamma_[tid] + beta_[tid];
    }
}

extern "C" void kernel_launch(void* const* d_in, const int* in_sizes, int n_in,
                              void* d_out, int out_size)
{
    const float* mol     = (const float*)d_in[0];
    const float* atom    = (const float*)d_in[1];
    const float* attend  = (const float*)d_in[2];
    const float* smask   = (const float*)d_in[3];
    const float* W1      = (const float*)d_in[4];
    const float* b1      = (const float*)d_in[5];
    const float* W2      = (const float*)d_in[6];
    const float* b2      = (const float*)d_in[7];
    const float* w_align = (const float*)d_in[8];
    const float* b_align = (const float*)d_in[9];
    const float* gamma_  = (const float*)d_in[10];
    const float* beta_   = (const float*)d_in[11];
    float* out = (float*)d_out;

    const int B = in_sizes[0] / DD;

    prep_w2<<<256, 128>>>(W2);

    cudaFuncSetAttribute(gnn_agg_kernel,
                         cudaFuncAttributeMaxDynamicSharedMemorySize, SMEM_BYTES);
    gnn_agg_kernel<<<B, 256, SMEM_BYTES>>>(mol, atom, attend, smask, W1, b1, W2, b2,
                                           w_align, b_align, gamma_, beta_, out);
}

// round 10
// speedup vs baseline: 2.3243x; 1.0322x over previous
#include <cuda_runtime.h>
#include <cuda_bf16.h>
#include <math.h>
#include <stdint.h>

#define DD 256
#define LL 128
#define NEG_SLOPE 0.2f
#define LN_EPS 1e-5f
#define KSTR 264            // smem row stride in bf16 halves (conflict-free)

// smem byte offsets
#define A_HI 0                              // [128][264] bf16 = 67584 B
#define A_LO 67584
#define W_HI 135168                         // [64][264] bf16 = 33792 B
#define W_LO 168960
#define MISC 202752                         // floats
// misc: qb 0, w 256, x 512, y 768, ctx 1024, s_part 1280(2*128), p 1536, red 1664(64)
static const int SMEM_BYTES = MISC + 1728 * 4;   // 209664

// precomputed W2 bf16 hi/lo, exact smem image (row-major, KSTR stride, pads 0)
__device__ __align__(16) __nv_bfloat16 g_Whi[256 * KSTR];
__device__ __align__(16) __nv_bfloat16 g_Wlo[256 * KSTR];
// k-split partial-S exchange scratch: 2048 CTAs x 8192 floats (L2-hot)
__device__ __align__(16) float g_sex[2048L * 8192];

__global__ void prep_w2(const float* __restrict__ W2) {
    const int r = blockIdx.x;
    for (int k = threadIdx.x; k < KSTR; k += blockDim.x) {
        float v = (k < DD) ? W2[(long)r * DD + k] : 0.f;
        __nv_bfloat16 h = __float2bfloat16(v);
        __nv_bfloat16 l = __float2bfloat16(v - __bfloat162float(h));
        g_Whi[(long)r * KSTR + k] = h;
        g_Wlo[(long)r * KSTR + k] = l;
    }
}

static __device__ __forceinline__ uint32_t smem_u32(const void* p) {
    uint32_t a;
    asm("{ .reg .u64 t; cvta.to.shared.u64 t, %1; cvt.u32.u64 %0, t; }"
        : "=r"(a) : "l"(p));
    return a;
}

#define LDSM_X4(r0, r1, r2, r3, addr) \
    asm volatile("ldmatrix.sync.aligned.m8n8.x4.shared.b16 {%0,%1,%2,%3}, [%4];" \
        : "=r"(r0), "=r"(r1), "=r"(r2), "=r"(r3) : "r"(addr))
#define MMA_BF16(c, a, b0, b1) \
    asm volatile("mma.sync.aligned.m16n8k16.row.col.f32.bf16.bf16.f32 " \
        "{%0,%1,%2,%3}, {%4,%5,%6,%7}, {%8,%9}, {%0,%1,%2,%3};" \
        : "+f"((c)[0]), "+f"((c)[1]), "+f"((c)[2]), "+f"((c)[3]) \
        : "r"((a)[0]), "r"((a)[1]), "r"((a)[2]), "r"((a)[3]), "r"(b0), "r"(b1))

__global__ __launch_bounds__(512, 1)
void gnn_agg_kernel(const float* __restrict__ mol,     // [B,D]
                    const float* __restrict__ atom,    // [B,L,D]
                    const float* __restrict__ attend,  // [B,L,1]
                    const float* __restrict__ smask,   // [B,L,1]
                    const float* __restrict__ W1,      // [D,D]
                    const float* __restrict__ b1,      // [D]
                    const float* __restrict__ W2,      // [D,D]
                    const float* __restrict__ b2,      // [D]
                    const float* __restrict__ w_align, // [D,1]
                    const float* __restrict__ b_align, // [1]
                    const float* __restrict__ gamma_,  // [D]
                    const float* __restrict__ beta_,   // [D]
                    float* __restrict__ out)           // [B,D]
{
    extern __shared__ char smem[];
    const uint32_t smb = smem_u32(smem);
    float* qb_s   = (float*)(smem + MISC);
    float* w_s    = qb_s + 256;
    float* x_s    = w_s  + 256;
    float* y_s    = x_s  + 256;
    float* ctx_s  = y_s  + 256;
    float* s_part = ctx_s + 256;  // [2][128]; also GEMV scratch later
    float* p_arr  = s_part + 256; // 128
    float* red    = p_arr + 128;  // 64

    const int b    = blockIdx.x;
    const int tid  = threadIdx.x;
    const int lane = tid & 31;
    const int wid  = tid >> 5;
    const int kh   = wid >> 3;    // k-half: warps 0-7 -> k[0,128), 8-15 -> k[128,256)
    const int wl   = wid & 7;
    const int mq   = wl >> 1;     // atom-quarter: rows [32mq, 32mq+32)
    const int nh   = wl & 1;      // n-half of 64-col chunk

    const float bal = b_align[0];

    // ---- overlap: warps 0-7 do qb GEMV, warps 8-15 stage A hi/lo ----
    if (tid < 256) {
        x_s[tid] = mol[(long)b * DD + tid];
        w_s[tid] = w_align[tid];
        asm volatile("bar.sync 1, 256;" ::: "memory");
        float acc = 0.f;
        const float4* w4 = (const float4*)(W1 + (long)tid * DD);
        #pragma unroll 8
        for (int k4 = 0; k4 < DD / 4; ++k4) {
            float4 wv = w4[k4];
            acc += x_s[4*k4+0]*wv.x + x_s[4*k4+1]*wv.y
                 + x_s[4*k4+2]*wv.z + x_s[4*k4+3]*wv.w;
        }
        qb_s[tid] = acc + b1[tid] + b2[tid];
    } else {
        for (int idx = tid - 256; idx < LL * (DD / 2); idx += 256) {
            const int r  = idx >> 7;
            const int kp = idx & 127;
            const float2 v = ((const float2*)(atom + ((long)b * LL + r) * DD))[kp];
            __nv_bfloat16 hx = __float2bfloat16(v.x);
            __nv_bfloat16 hy = __float2bfloat16(v.y);
            __nv_bfloat16 lx = __float2bfloat16(v.x - __bfloat162float(hx));
            __nv_bfloat16 ly = __float2bfloat16(v.y - __bfloat162float(hy));
            const int off = (r * KSTR + kp * 2) * 2;
            __nv_bfloat162 h; h.x = hx; h.y = hy;
            __nv_bfloat162 l; l.x = lx; l.y = ly;
            *(__nv_bfloat162*)(smem + A_HI + off) = h;
            *(__nv_bfloat162*)(smem + A_LO + off) = l;
        }
    }

    // fragment base addresses (validated mappings; + k-half offset)
    uint32_t addrAh[2], addrAl[2], addrBh[2], addrBl[2];
    {
        const uint32_t aColh = (lane >> 4) << 3;
        #pragma unroll
        for (int mt = 0; mt < 2; ++mt) {
            const uint32_t off = (((uint32_t)(32 * mq + 16 * mt) + (lane & 15)) * KSTR + aColh) * 2
                               + (uint32_t)kh * 256;
            addrAh[mt] = smb + A_HI + off;
            addrAl[mt] = smb + A_LO + off;
        }
        const uint32_t bIn16 = ((lane >> 4) << 3) + (lane & 7);
        const uint32_t bColh = ((lane >> 3) & 1) << 3;
        #pragma unroll
        for (int nt = 0; nt < 2; ++nt) {
            const uint32_t off = (((uint32_t)(32 * nh + 16 * nt) + bIn16) * KSTR + bColh) * 2
                               + (uint32_t)kh * 256;
            addrBh[nt] = smb + W_HI + off;
            addrBl[nt] = smb + W_LO + off;
        }
    }

    // stage W chunk 0 (all 512 threads)
    {
        const uint4* sh = (const uint4*)g_Whi;
        const uint4* sl = (const uint4*)g_Wlo;
        uint4* dh = (uint4*)(smem + W_HI);
        uint4* dl = (uint4*)(smem + W_LO);
        for (int idx = tid; idx < 2112; idx += 512) { dh[idx] = sh[idx]; dl[idx] = sl[idx]; }
    }
    __syncthreads();   // A + W0 ready, qb ready

    float sc[2][2] = {{0.f, 0.f}, {0.f, 0.f}};   // kh1 only: [mt][rowhalf]
    float2* gx2 = (float2*)g_sex + (long)b * 4096 + (wl * 16) * 32 + lane;

    #pragma unroll 1
    for (int nc = 0; nc < 4; ++nc) {
        float acc[2][4][4];
        #pragma unroll
        for (int mt = 0; mt < 2; ++mt)
            #pragma unroll
            for (int j = 0; j < 4; ++j)
                #pragma unroll
                for (int q = 0; q < 4; ++q) acc[mt][j][q] = 0.f;

        uint32_t fAh[2][2][4], fAl[2][2][4], fBh[2][2][4], fBl[2][2][4];
        #define LOADF(buf, ks) do {                                              \
            const uint32_t ko = (uint32_t)(ks) * 32;                             \
            LDSM_X4(fAh[buf][0][0], fAh[buf][0][1], fAh[buf][0][2], fAh[buf][0][3], addrAh[0] + ko); \
            LDSM_X4(fAh[buf][1][0], fAh[buf][1][1], fAh[buf][1][2], fAh[buf][1][3], addrAh[1] + ko); \
            LDSM_X4(fAl[buf][0][0], fAl[buf][0][1], fAl[buf][0][2], fAl[buf][0][3], addrAl[0] + ko); \
            LDSM_X4(fAl[buf][1][0], fAl[buf][1][1], fAl[buf][1][2], fAl[buf][1][3], addrAl[1] + ko); \
            LDSM_X4(fBh[buf][0][0], fBh[buf][0][1], fBh[buf][0][2], fBh[buf][0][3], addrBh[0] + ko); \
            LDSM_X4(fBh[buf][1][0], fBh[buf][1][1], fBh[buf][1][2], fBh[buf][1][3], addrBh[1] + ko); \
            LDSM_X4(fBl[buf][0][0], fBl[buf][0][1], fBl[buf][0][2], fBl[buf][0][3], addrBl[0] + ko); \
            LDSM_X4(fBl[buf][1][0], fBl[buf][1][1], fBl[buf][1][2], fBl[buf][1][3], addrBl[1] + ko); \
        } while (0)

        LOADF(0, 0);
        #pragma unroll
        for (int ks = 0; ks < 8; ++ks) {
            const int cur = ks & 1;
            if (ks < 7) LOADF(cur ^ 1, ks + 1);
            #pragma unroll
            for (int mt = 0; mt < 2; ++mt)
                #pragma unroll
                for (int nt = 0; nt < 2; ++nt) {
                    float* A0 = acc[mt][2 * nt + 0];
                    float* A1 = acc[mt][2 * nt + 1];
                    MMA_BF16(A0, fAh[cur][mt], fBh[cur][nt][0], fBh[cur][nt][1]);
                    MMA_BF16(A0, fAl[cur][mt], fBh[cur][nt][0], fBh[cur][nt][1]);
                    MMA_BF16(A0, fAh[cur][mt], fBl[cur][nt][0], fBl[cur][nt][1]);
                    MMA_BF16(A1, fAh[cur][mt], fBh[cur][nt][2], fBh[cur][nt][3]);
                    MMA_BF16(A1, fAl[cur][mt], fBh[cur][nt][2], fBh[cur][nt][3]);
                    MMA_BF16(A1, fAh[cur][mt], fBl[cur][nt][2], fBl[cur][nt][3]);
                }
        }
        #undef LOADF

        if (kh == 0) {   // ship raw S partials (coalesced float2 planes)
            #pragma unroll
            for (int mt = 0; mt < 2; ++mt)
                #pragma unroll
                for (int j = 0; j < 4; ++j)
                    #pragma unroll
                    for (int h = 0; h < 2; ++h)
                        gx2[(mt * 8 + j * 2 + h) * 32] =
                            make_float2(acc[mt][j][2 * h], acc[mt][j][2 * h + 1]);
        }
        __syncthreads();   // partials visible; MMAs done -> W smem free

        if (kh == 0) {
            if (nc < 3) {   // stage next W chunk while kh1 epilogues
                const uint4* sh = (const uint4*)(g_Whi + (long)(nc + 1) * 64 * KSTR);
                const uint4* sl = (const uint4*)(g_Wlo + (long)(nc + 1) * 64 * KSTR);
                uint4* dh = (uint4*)(smem + W_HI);
                uint4* dl = (uint4*)(smem + W_LO);
                for (int idx = tid; idx < 2112; idx += 256) { dh[idx] = sh[idx]; dl[idx] = sl[idx]; }
            }
        } else {           // add other half + leakyrelu fold
            #pragma unroll
            for (int mt = 0; mt < 2; ++mt)
                #pragma unroll
                for (int j = 0; j < 4; ++j) {
                    const int c = nc * 64 + nh * 32 + (j >> 1) * 16 + (j & 1) * 8 + (lane & 3) * 2;
                    const float q0 = qb_s[c], q1 = qb_s[c + 1];
                    const float w0 = w_s[c],  w1 = w_s[c + 1];
                    #pragma unroll
                    for (int h = 0; h < 2; ++h) {
                        const float2 o = gx2[(mt * 8 + j * 2 + h) * 32];
                        float v;
                        v = q0 + acc[mt][j][2*h]   + o.x; v = (v >= 0.f) ? v : NEG_SLOPE * v; sc[mt][h] += v * w0;
                        v = q1 + acc[mt][j][2*h+1] + o.y; v = (v >= 0.f) ? v : NEG_SLOPE * v; sc[mt][h] += v * w1;
                    }
                }
        }
        __syncthreads();   // next W staged / epilogue done
    }

    // kh1: quad-reduce score partials; unique (nh,row) writer
    if (kh == 1) {
        #pragma unroll
        for (int mt = 0; mt < 2; ++mt)
            #pragma unroll
            for (int rh = 0; rh < 2; ++rh) {
                float t = sc[mt][rh];
                t += __shfl_xor_sync(0xffffffffu, t, 1);
                t += __shfl_xor_sync(0xffffffffu, t, 2);
                if ((lane & 3) == 0)
                    s_part[nh * LL + 32 * mq + 16 * mt + (lane >> 2) + 8 * rh] = t;
            }
    }
    __syncthreads();

    // ---- softmax over 128 atoms (masked exps underflow to exactly 0) ----
    {
        float v = (tid < LL)
                ? (bal + s_part[tid] + s_part[LL + tid] + smask[(long)b * LL + tid])
                : -INFINITY;
        float t = v;
        #pragma unroll
        for (int off = 16; off; off >>= 1)
            t = fmaxf(t, __shfl_xor_sync(0xffffffffu, t, off));
        if (lane == 0) red[wid] = t;
        __syncthreads();
        float mx = red[0];
        #pragma unroll
        for (int w = 1; w < 16; ++w) mx = fmaxf(mx, red[w]);
        __syncthreads();

        float e = (tid < LL) ? __expf(v - mx) : 0.f;
        float ts = e;
        #pragma unroll
        for (int off = 16; off; off >>= 1)
            ts += __shfl_xor_sync(0xffffffffu, ts, off);
        if (lane == 0) red[wid] = ts;
        __syncthreads();
        float Z = red[0];
        #pragma unroll
        for (int w = 1; w < 16; ++w) Z += red[w];

        float att = (tid < LL) ? attend[(long)b * LL + tid] : 0.f;
        float pf = e * att / Z;
        if (tid < LL) p_arr[tid] = pf;
        float tc = pf;
        #pragma unroll
        for (int off = 16; off; off >>= 1)
            tc += __shfl_xor_sync(0xffffffffu, tc, off);
        if (lane == 0) red[16 + wid] = tc;
        __syncthreads();
        if (tid == 0) {
            float cb = red[16];
            for (int w = 1; w < 16; ++w) cb += red[16 + w];
            red[62] = cb;                 // sum of attn (b2 coefficient)
        }
    }
    __syncthreads();

    // ---- y[k] = sum_a attn[a]*atom[a,k] : atom-split across thread halves ----
    {
        const int k   = tid & 255;
        const int ah  = tid >> 8;         // 0: atoms 0-63, 1: atoms 64-127
        const float* Ab = atom + (long)b * LL * DD;
        float acc0 = 0.f, acc1 = 0.f;
        #pragma unroll 2
        for (int a = ah * 64; a < ah * 64 + 64; a += 2) {
            const float p0 = p_arr[a], p1 = p_arr[a + 1];
            if (p0 != 0.f) acc0 += p0 * Ab[(long)a * DD + k];
            if (p1 != 0.f) acc1 += p1 * Ab[(long)(a + 1) * DD + k];
        }
        if (ah == 0) y_s[k] = acc0 + acc1;
        else         s_part[k] = acc0 + acc1;
    }
    __syncthreads();
    if (tid < 256) y_s[tid] += s_part[tid];
    __syncthreads();

    // ---- ctx[d] = y @ W2.T + (sum attn)*b2 : k-split across thread halves ----
    {
        const int d   = tid & 255;
        const int kh2 = tid >> 8;
        float acc = (kh2 == 0) ? red[62] * b2[d] : 0.f;
        const float4* w4 = (const float4*)(W2 + (long)d * DD + kh2 * 128);
        const float*  yh = y_s + kh2 * 128;
        #pragma unroll 8
        for (int k4 = 0; k4 < 32; ++k4) {
            float4 wv = w4[k4];
            acc += yh[4*k4+0]*wv.x + yh[4*k4+1]*wv.y
                 + yh[4*k4+2]*wv.z + yh[4*k4+3]*wv.w;
        }
        if (kh2 == 0) ctx_s[d] = acc;
        else          s_part[d] = acc;
    }
    __syncthreads();
    if (tid < 256) ctx_s[tid] += s_part[tid];
    __syncthreads();

    // ---- LayerNorm over D (threads 0-255 hold values; all shuffle-reduce) ----
    {
        float v = (tid < 256) ? ctx_s[tid] : 0.f;
        float s1 = v;
        #pragma unroll
        for (int off = 16; off; off >>= 1)
            s1 += __shfl_xor_sync(0xffffffffu, s1, off);
        if (lane == 0) red[wid] = s1;
        __syncthreads();
        float total = red[0];
        #pragma unroll
        for (int w = 1; w < 16; ++w) total += red[w];
        const float mu = total * (1.f / DD);
        const float dv = v - mu;
        __syncthreads();

        float s2 = (tid < 256) ? dv * dv : 0.f;
        #pragma unroll
        for (int off = 16; off; off >>= 1)
            s2 += __shfl_xor_sync(0xffffffffu, s2, off);
        if (lane == 0) red[wid] = s2;
        __syncthreads();
        float tot2 = red[0];
        #pragma unroll
        for (int w = 1; w < 16; ++w) tot2 += red[w];
        const float var = tot2 * (1.f / DD);
        if (tid < 256)
            out[(long)b * DD + tid] = dv * rsqrtf(var + LN_EPS) * gamma_[tid] + beta_[tid];
    }
}

extern "C" void kernel_launch(void* const* d_in, const int* in_sizes, int n_in,
                              void* d_out, int out_size)
{
    const float* mol     = (const float*)d_in[0];
    const float* atom    = (const float*)d_in[1];
    const float* attend  = (const float*)d_in[2];
    const float* smask   = (const float*)d_in[3];
    const float* W1      = (const float*)d_in[4];
    const float* b1      = (const float*)d_in[5];
    const float* W2      = (const float*)d_in[6];
    const float* b2      = (const float*)d_in[7];
    const float* w_align = (const float*)d_in[8];
    const float* b_align = (const float*)d_in[9];
    const float* gamma_  = (const float*)d_in[10];
    const float* beta_   = (const float*)d_in[11];
    float* out = (float*)d_out;

    const int B = in_sizes[0] / DD;

    prep_w2<<<256, 128>>>(W2);

    cudaFuncSetAttribute(gnn_agg_kernel,
                         cudaFuncAttributeMaxDynamicSharedMemorySize, SMEM_BYTES);
    gnn_agg_kernel<<<B, 512, SMEM_BYTES>>>(mol, atom, attend, smask, W1, b1, W2, b2,
                                           w_align, b_align, gamma_, beta_, out);
}

// round 11
// speedup vs baseline: 2.4400x; 1.0498x over previous
#include <cuda_runtime.h>
#include <cuda_bf16.h>
#include <math.h>
#include <stdint.h>

#define DD 256
#define LL 128
#define NEG_SLOPE 0.2f
#define LN_EPS 1e-5f
#define ASTR 264            // A smem row stride in bf16 halves
#define WSTR 72             // W slice row stride in bf16 halves

// smem byte offsets
#define A_HI 0                               // [128][264] bf16 = 67584 B
#define A_LO 67584
#define WBUF 135168                          // 2 x (hi 18432 + lo 18432) = 73728
#define WSLICE 18432
#define WBUFSZ 36864
#define MISC 208896                          // floats
// misc floats: qb 0, w 256, x 512, y 768, ctx 1024, s_part 1280(4*128), p 1792, red 1920(64)
static const int SMEM_BYTES = MISC + 1984 * 4;   // 216832

// precomputed W2 bf16 hi/lo in k-sliced planes: [kc 4][d 256][WSTR 72], pads 0
__device__ __align__(16) __nv_bfloat16 g_Whi[4 * 256 * WSTR];
__device__ __align__(16) __nv_bfloat16 g_Wlo[4 * 256 * WSTR];

__global__ void prep_w2(const float* __restrict__ W2) {
    const int d = blockIdx.x;                 // 0..255 output dim
    for (int i = threadIdx.x; i < 4 * WSTR; i += blockDim.x) {
        const int kc = i / WSTR, k = i % WSTR;
        float v = (k < 64) ? W2[(long)d * DD + kc * 64 + k] : 0.f;
        __nv_bfloat16 h = __float2bfloat16(v);
        __nv_bfloat16 l = __float2bfloat16(v - __bfloat162float(h));
        g_Whi[((long)kc * 256 + d) * WSTR + k] = h;
        g_Wlo[((long)kc * 256 + d) * WSTR + k] = l;
    }
}

static __device__ __forceinline__ uint32_t smem_u32(const void* p) {
    uint32_t a;
    asm("{ .reg .u64 t; cvta.to.shared.u64 t, %1; cvt.u32.u64 %0, t; }"
        : "=r"(a) : "l"(p));
    return a;
}

#define CP_ASYNC16(dst, src) \
    asm volatile("cp.async.cg.shared.global [%0], [%1], 16;" :: "r"(dst), "l"(src) : "memory")
#define CP_COMMIT() asm volatile("cp.async.commit_group;" ::: "memory")
#define CP_WAIT1()  asm volatile("cp.async.wait_group 1;" ::: "memory")
#define CP_WAIT0()  asm volatile("cp.async.wait_group 0;" ::: "memory")

#define LDSM_X4(r0, r1, r2, r3, addr) \
    asm volatile("ldmatrix.sync.aligned.m8n8.x4.shared.b16 {%0,%1,%2,%3}, [%4];" \
        : "=r"(r0), "=r"(r1), "=r"(r2), "=r"(r3) : "r"(addr))
#define MMA_BF16(c, a, b0, b1) \
    asm volatile("mma.sync.aligned.m16n8k16.row.col.f32.bf16.bf16.f32 " \
        "{%0,%1,%2,%3}, {%4,%5,%6,%7}, {%8,%9}, {%0,%1,%2,%3};" \
        : "+f"((c)[0]), "+f"((c)[1]), "+f"((c)[2]), "+f"((c)[3]) \
        : "r"((a)[0]), "r"((a)[1]), "r"((a)[2]), "r"((a)[3]), "r"(b0), "r"(b1))

__global__ __launch_bounds__(512, 1)
void gnn_agg_kernel(const float* __restrict__ mol,     // [B,D]
                    const float* __restrict__ atom,    // [B,L,D]
                    const float* __restrict__ attend,  // [B,L,1]
                    const float* __restrict__ smask,   // [B,L,1]
                    const float* __restrict__ W1,      // [D,D]
                    const float* __restrict__ b1,      // [D]
                    const float* __restrict__ W2,      // [D,D]
                    const float* __restrict__ b2,      // [D]
                    const float* __restrict__ w_align, // [D,1]
                    const float* __restrict__ b_align, // [1]
                    const float* __restrict__ gamma_,  // [D]
                    const float* __restrict__ beta_,   // [D]
                    float* __restrict__ out)           // [B,D]
{
    extern __shared__ char smem[];
    const uint32_t smb = smem_u32(smem);
    float* qb_s   = (float*)(smem + MISC);
    float* w_s    = qb_s + 256;
    float* x_s    = w_s  + 256;
    float* y_s    = x_s  + 256;
    float* ctx_s  = y_s  + 256;
    float* s_part = ctx_s + 256;  // [4][128]
    float* p_arr  = s_part + 512; // 128
    float* red    = p_arr + 128;  // 64

    const int b    = blockIdx.x;
    const int tid  = threadIdx.x;
    const int lane = tid & 31;
    const int wid  = tid >> 5;
    const int mq   = wid >> 2;    // atom-quarter: rows [32mq, 32mq+32)
    const int nq   = wid & 3;     // 32-col group within 128-col pass

    const float bal = b_align[0];

    // ---- prologue: issue cp.async for W slice (np=0, kc=0) into buf 0 ----
    {
        const char* sH = (const char*)g_Whi;
        const char* sL = (const char*)g_Wlo;
        const uint32_t dH = smb + WBUF;
        const uint32_t dL = dH + WSLICE;
        for (int i = tid; i < 1152; i += 512) {
            CP_ASYNC16(dH + i * 16, sH + i * 16);
            CP_ASYNC16(dL + i * 16, sL + i * 16);
        }
        CP_COMMIT();
    }

    // ---- overlap: threads 0-255 do qb GEMV, 256-511 stage A hi/lo ----
    if (tid < 256) {
        x_s[tid] = mol[(long)b * DD + tid];
        w_s[tid] = w_align[tid];
        asm volatile("bar.sync 1, 256;" ::: "memory");
        float acc = 0.f;
        const float4* w4 = (const float4*)(W1 + (long)tid * DD);
        #pragma unroll 8
        for (int k4 = 0; k4 < DD / 4; ++k4) {
            float4 wv = w4[k4];
            acc += x_s[4*k4+0]*wv.x + x_s[4*k4+1]*wv.y
                 + x_s[4*k4+2]*wv.z + x_s[4*k4+3]*wv.w;
        }
        qb_s[tid] = acc + b1[tid] + b2[tid];
    } else {
        for (int idx = tid - 256; idx < LL * (DD / 2); idx += 256) {
            const int r  = idx >> 7;
            const int kp = idx & 127;
            const float2 v = ((const float2*)(atom + ((long)b * LL + r) * DD))[kp];
            __nv_bfloat16 hx = __float2bfloat16(v.x);
            __nv_bfloat16 hy = __float2bfloat16(v.y);
            __nv_bfloat16 lx = __float2bfloat16(v.x - __bfloat162float(hx));
            __nv_bfloat16 ly = __float2bfloat16(v.y - __bfloat162float(hy));
            const int off = (r * ASTR + kp * 2) * 2;
            __nv_bfloat162 h; h.x = hx; h.y = hy;
            __nv_bfloat162 l; l.x = lx; l.y = ly;
            *(__nv_bfloat162*)(smem + A_HI + off) = h;
            *(__nv_bfloat162*)(smem + A_LO + off) = l;
        }
    }

    // fragment base addresses (validated mappings)
    uint32_t addrAh[2], addrAl[2];
    uint32_t bOffW[2];              // W-slice-relative offsets for 2 n-tiles
    {
        const uint32_t aColh = (lane >> 4) << 3;
        #pragma unroll
        for (int mt = 0; mt < 2; ++mt) {
            const uint32_t off = (((uint32_t)(32 * mq + 16 * mt) + (lane & 15)) * ASTR + aColh) * 2;
            addrAh[mt] = smb + A_HI + off;
            addrAl[mt] = smb + A_LO + off;
        }
        const uint32_t bIn16 = ((lane >> 4) << 3) + (lane & 7);
        const uint32_t bColh = ((lane >> 3) & 1) << 3;
        #pragma unroll
        for (int nt = 0; nt < 2; ++nt)
            bOffW[nt] = (((uint32_t)(32 * nq + 16 * nt) + bIn16) * WSTR + bColh) * 2;
    }

    float sc[2][2] = {{0.f, 0.f}, {0.f, 0.f}};   // [mt][rowhalf], across both np

    #pragma unroll 1
    for (int np = 0; np < 2; ++np) {
        float acc[2][4][4];
        #pragma unroll
        for (int mt = 0; mt < 2; ++mt)
            #pragma unroll
            for (int j = 0; j < 4; ++j)
                #pragma unroll
                for (int q = 0; q < 4; ++q) acc[mt][j][q] = 0.f;

        #pragma unroll 1
        for (int kc = 0; kc < 4; ++kc) {
            const int s = np * 4 + kc;
            __syncthreads();     // prior stage's LDSMs done; buf (s+1)&1 free
            if (s + 1 < 8) {     // issue next W slice (fully overlapped)
                const int np2 = (s + 1) >> 2, kc2 = (s + 1) & 3;
                const char* sH = (const char*)(g_Whi + ((long)kc2 * 256 + np2 * 128) * WSTR);
                const char* sL = (const char*)(g_Wlo + ((long)kc2 * 256 + np2 * 128) * WSTR);
                const uint32_t dH = smb + WBUF + ((s + 1) & 1) * WBUFSZ;
                const uint32_t dL = dH + WSLICE;
                for (int i = tid; i < 1152; i += 512) {
                    CP_ASYNC16(dH + i * 16, sH + i * 16);
                    CP_ASYNC16(dL + i * 16, sL + i * 16);
                }
                CP_COMMIT();
                CP_WAIT1();      // slice s complete (s+1 still in flight)
            } else {
                CP_WAIT0();
            }
            __syncthreads();     // W slice s visible to all warps

            const uint32_t wbase = smb + WBUF + (s & 1) * WBUFSZ;
            const uint32_t addrBh0 = wbase + bOffW[0];
            const uint32_t addrBh1 = wbase + bOffW[1];
            const uint32_t addrBl0 = wbase + WSLICE + bOffW[0];
            const uint32_t addrBl1 = wbase + WSLICE + bOffW[1];
            const uint32_t aks = (uint32_t)kc * 128;   // 64 halves = 128 B

            uint32_t fAh[2][2][4], fAl[2][2][4], fBh[2][2][4], fBl[2][2][4];
            #define LOADF(buf, ks) do {                                          \
                const uint32_t koA = aks + (uint32_t)(ks) * 32;                  \
                const uint32_t koB = (uint32_t)(ks) * 32;                        \
                LDSM_X4(fAh[buf][0][0], fAh[buf][0][1], fAh[buf][0][2], fAh[buf][0][3], addrAh[0] + koA); \
                LDSM_X4(fAh[buf][1][0], fAh[buf][1][1], fAh[buf][1][2], fAh[buf][1][3], addrAh[1] + koA); \
                LDSM_X4(fAl[buf][0][0], fAl[buf][0][1], fAl[buf][0][2], fAl[buf][0][3], addrAl[0] + koA); \
                LDSM_X4(fAl[buf][1][0], fAl[buf][1][1], fAl[buf][1][2], fAl[buf][1][3], addrAl[1] + koA); \
                LDSM_X4(fBh[buf][0][0], fBh[buf][0][1], fBh[buf][0][2], fBh[buf][0][3], addrBh0 + koB); \
                LDSM_X4(fBh[buf][1][0], fBh[buf][1][1], fBh[buf][1][2], fBh[buf][1][3], addrBh1 + koB); \
                LDSM_X4(fBl[buf][0][0], fBl[buf][0][1], fBl[buf][0][2], fBl[buf][0][3], addrBl0 + koB); \
                LDSM_X4(fBl[buf][1][0], fBl[buf][1][1], fBl[buf][1][2], fBl[buf][1][3], addrBl1 + koB); \
            } while (0)

            LOADF(0, 0);
            #pragma unroll
            for (int ks = 0; ks < 4; ++ks) {
                const int cur = ks & 1;
                if (ks < 3) LOADF(cur ^ 1, ks + 1);
                #pragma unroll
                for (int mt = 0; mt < 2; ++mt)
                    #pragma unroll
                    for (int nt = 0; nt < 2; ++nt) {
                        float* A0 = acc[mt][2 * nt + 0];
                        float* A1 = acc[mt][2 * nt + 1];
                        MMA_BF16(A0, fAh[cur][mt], fBh[cur][nt][0], fBh[cur][nt][1]);
                        MMA_BF16(A0, fAl[cur][mt], fBh[cur][nt][0], fBh[cur][nt][1]);
                        MMA_BF16(A0, fAh[cur][mt], fBl[cur][nt][0], fBl[cur][nt][1]);
                        MMA_BF16(A1, fAh[cur][mt], fBh[cur][nt][2], fBh[cur][nt][3]);
                        MMA_BF16(A1, fAl[cur][mt], fBh[cur][nt][2], fBh[cur][nt][3]);
                        MMA_BF16(A1, fAh[cur][mt], fBl[cur][nt][2], fBl[cur][nt][3]);
                    }
            }
            #undef LOADF
        }

        // epilogue for this 128-col pass: fold leakyrelu(qb+S)*w_align
        #pragma unroll
        for (int mt = 0; mt < 2; ++mt)
            #pragma unroll
            for (int j = 0; j < 4; ++j) {
                const int c = np * 128 + nq * 32 + (j >> 1) * 16 + (j & 1) * 8 + (lane & 3) * 2;
                const float q0 = qb_s[c], q1 = qb_s[c + 1];
                const float w0 = w_s[c],  w1 = w_s[c + 1];
                float v;
                v = q0 + acc[mt][j][0]; v = (v >= 0.f) ? v : NEG_SLOPE * v; sc[mt][0] += v * w0;
                v = q1 + acc[mt][j][1]; v = (v >= 0.f) ? v : NEG_SLOPE * v; sc[mt][0] += v * w1;
                v = q0 + acc[mt][j][2]; v = (v >= 0.f) ? v : NEG_SLOPE * v; sc[mt][1] += v * w0;
                v = q1 + acc[mt][j][3]; v = (v >= 0.f) ? v : NEG_SLOPE * v; sc[mt][1] += v * w1;
            }
    }

    // quad-reduce score partials; unique (nq,row) writer
    #pragma unroll
    for (int mt = 0; mt < 2; ++mt)
        #pragma unroll
        for (int rh = 0; rh < 2; ++rh) {
            float t = sc[mt][rh];
            t += __shfl_xor_sync(0xffffffffu, t, 1);
            t += __shfl_xor_sync(0xffffffffu, t, 2);
            if ((lane & 3) == 0)
                s_part[nq * LL + 32 * mq + 16 * mt + (lane >> 2) + 8 * rh] = t;
        }
    __syncthreads();

    // ---- softmax over 128 atoms (masked exps underflow to exactly 0) ----
    {
        float v = (tid < LL)
                ? (bal + (s_part[tid] + s_part[LL + tid])
                       + (s_part[2 * LL + tid] + s_part[3 * LL + tid])
                       + smask[(long)b * LL + tid])
                : -INFINITY;
        float t = v;
        #pragma unroll
        for (int off = 16; off; off >>= 1)
            t = fmaxf(t, __shfl_xor_sync(0xffffffffu, t, off));
        if (lane == 0) red[wid] = t;
        __syncthreads();
        float mx = red[0];
        #pragma unroll
        for (int w = 1; w < 16; ++w) mx = fmaxf(mx, red[w]);
        __syncthreads();

        float e = (tid < LL) ? __expf(v - mx) : 0.f;
        float ts = e;
        #pragma unroll
        for (int off = 16; off; off >>= 1)
            ts += __shfl_xor_sync(0xffffffffu, ts, off);
        if (lane == 0) red[wid] = ts;
        __syncthreads();
        float Z = red[0];
        #pragma unroll
        for (int w = 1; w < 16; ++w) Z += red[w];

        float att = (tid < LL) ? attend[(long)b * LL + tid] : 0.f;
        float pf = e * att / Z;
        if (tid < LL) p_arr[tid] = pf;
        float tc = pf;
        #pragma unroll
        for (int off = 16; off; off >>= 1)
            tc += __shfl_xor_sync(0xffffffffu, tc, off);
        if (lane == 0) red[16 + wid] = tc;
        __syncthreads();
        if (tid == 0) {
            float cb = red[16];
            for (int w = 1; w < 16; ++w) cb += red[16 + w];
            red[62] = cb;                 // sum of attn (b2 coefficient)
        }
    }
    __syncthreads();

    // ---- y[k] = sum_a attn[a]*atom[a,k] : atom-split across thread halves ----
    {
        const int k   = tid & 255;
        const int ah  = tid >> 8;
        const float* Ab = atom + (long)b * LL * DD;
        float acc0 = 0.f, acc1 = 0.f;
        #pragma unroll 2
        for (int a = ah * 64; a < ah * 64 + 64; a += 2) {
            const float p0 = p_arr[a], p1 = p_arr[a + 1];
            if (p0 != 0.f) acc0 += p0 * Ab[(long)a * DD + k];
            if (p1 != 0.f) acc1 += p1 * Ab[(long)(a + 1) * DD + k];
        }
        if (ah == 0) y_s[k] = acc0 + acc1;
        else         s_part[k] = acc0 + acc1;
    }
    __syncthreads();
    if (tid < 256) y_s[tid] += s_part[tid];
    __syncthreads();

    // ---- ctx[d] = y @ W2.T + (sum attn)*b2 : k-split across thread halves ----
    {
        const int d   = tid & 255;
        const int kh2 = tid >> 8;
        float acc = (kh2 == 0) ? red[62] * b2[d] : 0.f;
        const float4* w4 = (const float4*)(W2 + (long)d * DD + kh2 * 128);
        const float*  yh = y_s + kh2 * 128;
        #pragma unroll 8
        for (int k4 = 0; k4 < 32; ++k4) {
            float4 wv = w4[k4];
            acc += yh[4*k4+0]*wv.x + yh[4*k4+1]*wv.y
                 + yh[4*k4+2]*wv.z + yh[4*k4+3]*wv.w;
        }
        if (kh2 == 0) ctx_s[d] = acc;
        else          s_part[d] = acc;
    }
    __syncthreads();
    if (tid < 256) ctx_s[tid] += s_part[tid];
    __syncthreads();

    // ---- LayerNorm over D ----
    {
        float v = (tid < 256) ? ctx_s[tid] : 0.f;
        float s1 = v;
        #pragma unroll
        for (int off = 16; off; off >>= 1)
            s1 += __shfl_xor_sync(0xffffffffu, s1, off);
        if (lane == 0) red[wid] = s1;
        __syncthreads();
        float total = red[0];
        #pragma unroll
        for (int w = 1; w < 16; ++w) total += red[w];
        const float mu = total * (1.f / DD);
        const float dv = v - mu;
        __syncthreads();

        float s2 = (tid < 256) ? dv * dv : 0.f;
        #pragma unroll
        for (int off = 16; off; off >>= 1)
            s2 += __shfl_xor_sync(0xffffffffu, s2, off);
        if (lane == 0) red[wid] = s2;
        __syncthreads();
        float tot2 = red[0];
        #pragma unroll
        for (int w = 1; w < 16; ++w) tot2 += red[w];
        const float var = tot2 * (1.f / DD);
        if (tid < 256)
            out[(long)b * DD + tid] = dv * rsqrtf(var + LN_EPS) * gamma_[tid] + beta_[tid];
    }
}

extern "C" void kernel_launch(void* const* d_in, const int* in_sizes, int n_in,
                              void* d_out, int out_size)
{
    const float* mol     = (const float*)d_in[0];
    const float* atom    = (const float*)d_in[1];
    const float* attend  = (const float*)d_in[2];
    const float* smask   = (const float*)d_in[3];
    const float* W1      = (const float*)d_in[4];
    const float* b1      = (const float*)d_in[5];
    const float* W2      = (const float*)d_in[6];
    const float* b2      = (const float*)d_in[7];
    const float* w_align = (const float*)d_in[8];
    const float* b_align = (const float*)d_in[9];
    const float* gamma_  = (const float*)d_in[10];
    const float* beta_   = (const float*)d_in[11];
    float* out = (float*)d_out;

    const int B = in_sizes[0] / DD;

    prep_w2<<<256, 128>>>(W2);

    cudaFuncSetAttribute(gnn_agg_kernel,
                         cudaFuncAttributeMaxDynamicSharedMemorySize, SMEM_BYTES);
    gnn_agg_kernel<<<B, 512, SMEM_BYTES>>>(mol, atom, attend, smask, W1, b1, W2, b2,
                                           w_align, b_align, gamma_, beta_, out);
}

// round 12
// speedup vs baseline: 3.7870x; 1.5520x over previous
#include <cuda_runtime.h>
#include <cuda_bf16.h>
#include <math.h>
#include <stdint.h>

#define DD 256
#define LL 128
#define NEG_SLOPE 0.2f
#define LN_EPS 1e-5f
#define ASTR 264            // A smem row stride in bf16 halves
#define WSTR 72             // W plane row stride in bf16 halves

// K1 smem byte offsets (dynamic)
#define A_HI 0                               // [64][264] bf16 = 33792 B
#define A_LO 33792
#define WS   67584                           // slice [128][72]: hi 18432 + lo 18432
#define WS_LO_OFF 18432
#define MISC 104448                          // floats
// misc floats: qb 256, w 256, s_part 256(4*64), p 64, red 32  = 864
static const int K1_SMEM = MISC + 864 * 4;   // 107904

// precomputed W2 bf16 hi/lo planes: [kc 4][d 256][WSTR 72], pads 0
__device__ __align__(16) __nv_bfloat16 g_Whi[4 * 256 * WSTR];
__device__ __align__(16) __nv_bfloat16 g_Wlo[4 * 256 * WSTR];
__device__ __align__(16) float g_qb[2048L * 256];       // qb = mol@W1^T + b1 + b2
__device__ __align__(16) float g_y [2048L * 2 * 256];   // per-half unnormalized y
__device__ __align__(16) float g_st[2048L * 2 * 4];     // per-half (m, Z, sumattn)

__global__ void prep_w2(const float* __restrict__ W2) {
    const int d = blockIdx.x;
    for (int i = threadIdx.x; i < 4 * WSTR; i += blockDim.x) {
        const int kc = i / WSTR, k = i % WSTR;
        float v = (k < 64) ? W2[(long)d * DD + kc * 64 + k] : 0.f;
        __nv_bfloat16 h = __float2bfloat16(v);
        __nv_bfloat16 l = __float2bfloat16(v - __bfloat162float(h));
        g_Whi[((long)kc * 256 + d) * WSTR + k] = h;
        g_Wlo[((long)kc * 256 + d) * WSTR + k] = l;
    }
}

__global__ __launch_bounds__(256)
void prep_qb(const float* __restrict__ mol, const float* __restrict__ W1,
             const float* __restrict__ b1, const float* __restrict__ b2) {
    __shared__ __align__(16) float mol_s[8 * 256];
    const int bm0 = blockIdx.x * 8;
    const int tid = threadIdx.x;
    for (int i = tid; i < 8 * 256; i += 256) mol_s[i] = mol[(long)bm0 * 256 + i];
    __syncthreads();
    const int d = tid;
    const float bb = b1[d] + b2[d];
    float acc[8];
    #pragma unroll
    for (int m = 0; m < 8; ++m) acc[m] = bb;
    const float4* w4 = (const float4*)(W1 + (long)d * 256);
    for (int k4 = 0; k4 < 64; ++k4) {
        const float4 wv = w4[k4];
        #pragma unroll
        for (int m = 0; m < 8; ++m) {
            const float4 yv = *(const float4*)(mol_s + m * 256 + k4 * 4);
            acc[m] += yv.x * wv.x + yv.y * wv.y + yv.z * wv.z + yv.w * wv.w;
        }
    }
    #pragma unroll
    for (int m = 0; m < 8; ++m) g_qb[(long)(bm0 + m) * 256 + d] = acc[m];
}

static __device__ __forceinline__ uint32_t smem_u32(const void* p) {
    uint32_t a;
    asm("{ .reg .u64 t; cvta.to.shared.u64 t, %1; cvt.u32.u64 %0, t; }"
        : "=r"(a) : "l"(p));
    return a;
}

#define CP_ASYNC16(dst, src) \
    asm volatile("cp.async.cg.shared.global [%0], [%1], 16;" :: "r"(dst), "l"(src) : "memory")
#define CP_COMMIT() asm volatile("cp.async.commit_group;" ::: "memory")
#define CP_WAIT0()  asm volatile("cp.async.wait_group 0;" ::: "memory")

#define LDSM_X4(r0, r1, r2, r3, addr) \
    asm volatile("ldmatrix.sync.aligned.m8n8.x4.shared.b16 {%0,%1,%2,%3}, [%4];" \
        : "=r"(r0), "=r"(r1), "=r"(r2), "=r"(r3) : "r"(addr))
#define MMA_BF16(c, a, b0, b1) \
    asm volatile("mma.sync.aligned.m16n8k16.row.col.f32.bf16.bf16.f32 " \
        "{%0,%1,%2,%3}, {%4,%5,%6,%7}, {%8,%9}, {%0,%1,%2,%3};" \
        : "+f"((c)[0]), "+f"((c)[1]), "+f"((c)[2]), "+f"((c)[3]) \
        : "r"((a)[0]), "r"((a)[1]), "r"((a)[2]), "r"((a)[3]), "r"(b0), "r"(b1))

// K1: per-CTA = 64 atoms of one molecule. Scores -> half softmax stats + y_half.
__global__ __launch_bounds__(256, 2)
void k1_scores(const float* __restrict__ atom,    // [B,L,D]
               const float* __restrict__ attend,  // [B,L,1]
               const float* __restrict__ smask,   // [B,L,1]
               const float* __restrict__ w_align, // [D,1]
               const float* __restrict__ b_align) // [1]
{
    extern __shared__ char smem[];
    const uint32_t smb = smem_u32(smem);
    float* qb_s   = (float*)(smem + MISC);
    float* w_s    = qb_s + 256;
    float* s_part = w_s + 256;    // [4][64]
    float* p_arr  = s_part + 256; // 64
    float* red    = p_arr + 64;   // 32

    const int bx   = blockIdx.x;
    const int b    = bx >> 1;
    const int h    = bx & 1;
    const int tid  = threadIdx.x;
    const int lane = tid & 31;
    const int wid  = tid >> 5;
    const int mq   = wid >> 2;    // atom 32-row half within the 64-atom tile
    const int nq   = wid & 3;     // 32-col group within 128-col slice

    // prologue: issue W slice (np=0, kc=0) cp.asyncs
    {
        const char* sH = (const char*)g_Whi;
        const char* sL = (const char*)g_Wlo;
        const uint32_t dH = smb + WS;
        const uint32_t dL = dH + WS_LO_OFF;
        for (int i = tid; i < 1152; i += 256) {
            CP_ASYNC16(dH + i * 16, sH + i * 16);
            CP_ASYNC16(dL + i * 16, sL + i * 16);
        }
        CP_COMMIT();
    }

    qb_s[tid] = g_qb[(long)b * 256 + tid];
    w_s[tid]  = w_align[tid];
    const float bal = b_align[0];

    // stage A = 64 atoms as bf16 hi/lo
    const long abase = ((long)b * LL + 64 * h) * DD;
    for (int idx = tid; idx < 64 * (DD / 2); idx += 256) {
        const int r  = idx >> 7;
        const int kp = idx & 127;
        const float2 v = ((const float2*)(atom + abase + (long)r * DD))[kp];
        __nv_bfloat16 hx = __float2bfloat16(v.x);
        __nv_bfloat16 hy = __float2bfloat16(v.y);
        __nv_bfloat16 lx = __float2bfloat16(v.x - __bfloat162float(hx));
        __nv_bfloat16 ly = __float2bfloat16(v.y - __bfloat162float(hy));
        const int off = (r * ASTR + kp * 2) * 2;
        __nv_bfloat162 hv; hv.x = hx; hv.y = hy;
        __nv_bfloat162 lv; lv.x = lx; lv.y = ly;
        *(__nv_bfloat162*)(smem + A_HI + off) = hv;
        *(__nv_bfloat162*)(smem + A_LO + off) = lv;
    }

    // fragment base addresses (validated mappings)
    uint32_t addrAh[2], addrAl[2], addrBh[2], addrBl[2];
    {
        const uint32_t aColh = (lane >> 4) << 3;
        #pragma unroll
        for (int mt = 0; mt < 2; ++mt) {
            const uint32_t off = (((uint32_t)(32 * mq + 16 * mt) + (lane & 15)) * ASTR + aColh) * 2;
            addrAh[mt] = smb + A_HI + off;
            addrAl[mt] = smb + A_LO + off;
        }
        const uint32_t bIn16 = ((lane >> 4) << 3) + (lane & 7);
        const uint32_t bColh = ((lane >> 3) & 1) << 3;
        #pragma unroll
        for (int nt = 0; nt < 2; ++nt) {
            const uint32_t off = (((uint32_t)(32 * nq + 16 * nt) + bIn16) * WSTR + bColh) * 2;
            addrBh[nt] = smb + WS + off;
            addrBl[nt] = smb + WS + WS_LO_OFF + off;
        }
    }
    __syncthreads();   // A + qb + w ready (W slice 0 in flight)

    float sc[2][2] = {{0.f, 0.f}, {0.f, 0.f}};   // [mt][rowhalf]

    #pragma unroll 1
    for (int np = 0; np < 2; ++np) {
        float acc[2][4][4];
        #pragma unroll
        for (int mt = 0; mt < 2; ++mt)
            #pragma unroll
            for (int j = 0; j < 4; ++j)
                #pragma unroll
                for (int q = 0; q < 4; ++q) acc[mt][j][q] = 0.f;

        #pragma unroll 1
        for (int kc = 0; kc < 4; ++kc) {
            const int s = np * 4 + kc;
            if (s > 0) {
                __syncthreads();   // prior slice's LDSMs done
                const char* sH = (const char*)(g_Whi + ((long)kc * 256 + np * 128) * WSTR);
                const char* sL = (const char*)(g_Wlo + ((long)kc * 256 + np * 128) * WSTR);
                const uint32_t dH = smb + WS;
                const uint32_t dL = dH + WS_LO_OFF;
                for (int i = tid; i < 1152; i += 256) {
                    CP_ASYNC16(dH + i * 16, sH + i * 16);
                    CP_ASYNC16(dL + i * 16, sL + i * 16);
                }
                CP_COMMIT();
            }
            CP_WAIT0();
            __syncthreads();       // slice s visible

            const uint32_t aks = (uint32_t)kc * 128;

            uint32_t fAh[2][2][4], fAl[2][2][4], fBh[2][2][4], fBl[2][2][4];
            #define LOADF(buf, ks) do {                                          \
                const uint32_t koA = aks + (uint32_t)(ks) * 32;                  \
                const uint32_t koB = (uint32_t)(ks) * 32;                        \
                LDSM_X4(fAh[buf][0][0], fAh[buf][0][1], fAh[buf][0][2], fAh[buf][0][3], addrAh[0] + koA); \
                LDSM_X4(fAh[buf][1][0], fAh[buf][1][1], fAh[buf][1][2], fAh[buf][1][3], addrAh[1] + koA); \
                LDSM_X4(fAl[buf][0][0], fAl[buf][0][1], fAl[buf][0][2], fAl[buf][0][3], addrAl[0] + koA); \
                LDSM_X4(fAl[buf][1][0], fAl[buf][1][1], fAl[buf][1][2], fAl[buf][1][3], addrAl[1] + koA); \
                LDSM_X4(fBh[buf][0][0], fBh[buf][0][1], fBh[buf][0][2], fBh[buf][0][3], addrBh[0] + koB); \
                LDSM_X4(fBh[buf][1][0], fBh[buf][1][1], fBh[buf][1][2], fBh[buf][1][3], addrBh[1] + koB); \
                LDSM_X4(fBl[buf][0][0], fBl[buf][0][1], fBl[buf][0][2], fBl[buf][0][3], addrBl[0] + koB); \
                LDSM_X4(fBl[buf][1][0], fBl[buf][1][1], fBl[buf][1][2], fBl[buf][1][3], addrBl[1] + koB); \
            } while (0)

            LOADF(0, 0);
            #pragma unroll
            for (int ks = 0; ks < 4; ++ks) {
                const int cur = ks & 1;
                if (ks < 3) LOADF(cur ^ 1, ks + 1);
                #pragma unroll
                for (int mt = 0; mt < 2; ++mt)
                    #pragma unroll
                    for (int nt = 0; nt < 2; ++nt) {
                        float* A0 = acc[mt][2 * nt + 0];
                        float* A1 = acc[mt][2 * nt + 1];
                        MMA_BF16(A0, fAh[cur][mt], fBh[cur][nt][0], fBh[cur][nt][1]);
                        MMA_BF16(A0, fAl[cur][mt], fBh[cur][nt][0], fBh[cur][nt][1]);
                        MMA_BF16(A0, fAh[cur][mt], fBl[cur][nt][0], fBl[cur][nt][1]);
                        MMA_BF16(A1, fAh[cur][mt], fBh[cur][nt][2], fBh[cur][nt][3]);
                        MMA_BF16(A1, fAl[cur][mt], fBh[cur][nt][2], fBh[cur][nt][3]);
                        MMA_BF16(A1, fAh[cur][mt], fBl[cur][nt][2], fBl[cur][nt][3]);
                    }
            }
            #undef LOADF
        }

        // fold leakyrelu(qb + S) * w_align into per-row partials
        #pragma unroll
        for (int mt = 0; mt < 2; ++mt)
            #pragma unroll
            for (int j = 0; j < 4; ++j) {
                const int c = np * 128 + nq * 32 + (j >> 1) * 16 + (j & 1) * 8 + (lane & 3) * 2;
                const float q0 = qb_s[c], q1 = qb_s[c + 1];
                const float w0 = w_s[c],  w1 = w_s[c + 1];
                float v;
                v = q0 + acc[mt][j][0]; v = (v >= 0.f) ? v : NEG_SLOPE * v; sc[mt][0] += v * w0;
                v = q1 + acc[mt][j][1]; v = (v >= 0.f) ? v : NEG_SLOPE * v; sc[mt][0] += v * w1;
                v = q0 + acc[mt][j][2]; v = (v >= 0.f) ? v : NEG_SLOPE * v; sc[mt][1] += v * w0;
                v = q1 + acc[mt][j][3]; v = (v >= 0.f) ? v : NEG_SLOPE * v; sc[mt][1] += v * w1;
            }
    }

    // quad-reduce; unique (nq,row) writer into s_part[4][64]
    #pragma unroll
    for (int mt = 0; mt < 2; ++mt)
        #pragma unroll
        for (int rh = 0; rh < 2; ++rh) {
            float t = sc[mt][rh];
            t += __shfl_xor_sync(0xffffffffu, t, 1);
            t += __shfl_xor_sync(0xffffffffu, t, 2);
            if ((lane & 3) == 0)
                s_part[nq * 64 + 32 * mq + 16 * mt + (lane >> 2) + 8 * rh] = t;
        }
    __syncthreads();

    // half-softmax stats over 64 atoms
    {
        float v = (tid < 64)
                ? (bal + (s_part[tid] + s_part[64 + tid])
                       + (s_part[128 + tid] + s_part[192 + tid])
                       + smask[(long)b * LL + 64 * h + tid])
                : -INFINITY;
        float t = v;
        #pragma unroll
        for (int off = 16; off; off >>= 1)
            t = fmaxf(t, __shfl_xor_sync(0xffffffffu, t, off));
        if (lane == 0) red[wid] = t;
        __syncthreads();
        float mx = red[0];
        #pragma unroll
        for (int w = 1; w < 8; ++w) mx = fmaxf(mx, red[w]);
        __syncthreads();

        float e = (tid < 64) ? __expf(v - mx) : 0.f;
        float att = (tid < 64) ? attend[(long)b * LL + 64 * h + tid] : 0.f;
        float pf = e * att;
        if (tid < 64) p_arr[tid] = pf;

        float ts = e;
        #pragma unroll
        for (int off = 16; off; off >>= 1)
            ts += __shfl_xor_sync(0xffffffffu, ts, off);
        if (lane == 0) red[8 + wid] = ts;
        float ta = pf;
        #pragma unroll
        for (int off = 16; off; off >>= 1)
            ta += __shfl_xor_sync(0xffffffffu, ta, off);
        if (lane == 0) red[16 + wid] = ta;
        __syncthreads();
        if (tid == 0) {
            float Z = 0.f, sa = 0.f;
            for (int w = 0; w < 8; ++w) { Z += red[8 + w]; sa += red[16 + w]; }
            float* st = g_st + (long)(b * 2 + h) * 4;
            st[0] = mx; st[1] = Z; st[2] = sa;
        }
    }
    __syncthreads();

    // y_half[k] = sum_a pf[a] * atom[a,k] (unnormalized, masked)
    {
        const float* Ab = atom + abase;
        float acc0 = 0.f, acc1 = 0.f;
        #pragma unroll 2
        for (int a = 0; a < 64; a += 2) {
            const float p0 = p_arr[a], p1 = p_arr[a + 1];
            if (p0 != 0.f) acc0 += p0 * Ab[(long)a * DD + tid];
            if (p1 != 0.f) acc1 += p1 * Ab[(long)(a + 1) * DD + tid];
        }
        g_y[((long)(b * 2 + h)) * 256 + tid] = acc0 + acc1;
    }
}

// K2: flash-combine halves + ctx GEMV + LayerNorm. 8 molecules per CTA.
__global__ __launch_bounds__(256)
void k2_tail(const float* __restrict__ W2, const float* __restrict__ b2,
             const float* __restrict__ gamma_, const float* __restrict__ beta_,
             float* __restrict__ out)
{
    __shared__ __align__(16) float y_s[8 * 256];
    __shared__ __align__(16) float ctx_s[8 * 256];
    __shared__ float cs[8][4];
    const int bm0 = blockIdx.x * 8;
    const int tid = threadIdx.x;
    const int lane = tid & 31;
    const int wid = tid >> 5;

    if (tid < 8) {
        const float* st = g_st + (long)(bm0 + tid) * 8;
        const float m0 = st[0], Z0 = st[1], sa0 = st[2];
        const float m1 = st[4], Z1 = st[5], sa1 = st[6];
        const float mx = fmaxf(m0, m1);
        const float s0 = __expf(m0 - mx), s1 = __expf(m1 - mx);
        const float Z = Z0 * s0 + Z1 * s1;
        const float c0 = s0 / Z, c1 = s1 / Z;
        cs[tid][0] = c0; cs[tid][1] = c1;
        cs[tid][2] = sa0 * c0 + sa1 * c1;   // sum of attn
    }
    __syncthreads();
    for (int i = tid; i < 8 * 256; i += 256) {
        const int m = i >> 8, k = i & 255;
        y_s[i] = g_y[(long)(bm0 + m) * 2 * 256 + k] * cs[m][0]
               + g_y[((long)(bm0 + m) * 2 + 1) * 256 + k] * cs[m][1];
    }
    __syncthreads();
    {
        const int d = tid;
        const float b2d = b2[d];
        float acc[8];
        #pragma unroll
        for (int m = 0; m < 8; ++m) acc[m] = cs[m][2] * b2d;
        const float4* w4 = (const float4*)(W2 + (long)d * 256);
        for (int k4 = 0; k4 < 64; ++k4) {
            const float4 wv = w4[k4];
            #pragma unroll
            for (int m = 0; m < 8; ++m) {
                const float4 yv = *(const float4*)(y_s + m * 256 + k4 * 4);
                acc[m] += yv.x * wv.x + yv.y * wv.y + yv.z * wv.z + yv.w * wv.w;
            }
        }
        #pragma unroll
        for (int m = 0; m < 8; ++m) ctx_s[m * 256 + d] = acc[m];
    }
    __syncthreads();
    {   // LN: warp w -> molecule w
        float vals[8];
        float s1 = 0.f;
        #pragma unroll
        for (int j = 0; j < 8; ++j) {
            vals[j] = ctx_s[wid * 256 + lane + 32 * j];
            s1 += vals[j];
        }
        #pragma unroll
        for (int off = 16; off; off >>= 1)
            s1 += __shfl_xor_sync(0xffffffffu, s1, off);
        const float mu = s1 * (1.f / 256.f);
        float s2 = 0.f;
        #pragma unroll
        for (int j = 0; j < 8; ++j) {
            const float d = vals[j] - mu;
            s2 += d * d;
        }
        #pragma unroll
        for (int off = 16; off; off >>= 1)
            s2 += __shfl_xor_sync(0xffffffffu, s2, off);
        const float inv = rsqrtf(s2 * (1.f / 256.f) + LN_EPS);
        #pragma unroll
        for (int j = 0; j < 8; ++j) {
            const int d = lane + 32 * j;
            out[(long)(bm0 + wid) * 256 + d] =
                (vals[j] - mu) * inv * gamma_[d] + beta_[d];
        }
    }
}

extern "C" void kernel_launch(void* const* d_in, const int* in_sizes, int n_in,
                              void* d_out, int out_size)
{
    const float* mol     = (const float*)d_in[0];
    const float* atom    = (const float*)d_in[1];
    const float* attend  = (const float*)d_in[2];
    const float* smask   = (const float*)d_in[3];
    const float* W1      = (const float*)d_in[4];
    const float* b1      = (const float*)d_in[5];
    const float* W2      = (const float*)d_in[6];
    const float* b2      = (const float*)d_in[7];
    const float* w_align = (const float*)d_in[8];
    const float* b_align = (const float*)d_in[9];
    const float* gamma_  = (const float*)d_in[10];
    const float* beta_   = (const float*)d_in[11];
    float* out = (float*)d_out;

    const int B = in_sizes[0] / DD;

    prep_w2<<<256, 128>>>(W2);
    prep_qb<<<B / 8, 256>>>(mol, W1, b1, b2);

    cudaFuncSetAttribute(k1_scores,
                         cudaFuncAttributeMaxDynamicSharedMemorySize, K1_SMEM);
    k1_scores<<<B * 2, 256, K1_SMEM>>>(atom, attend, smask, w_align, b_align);

    k2_tail<<<B / 8, 256>>>(W2, b2, gamma_, beta_, out);
}

// round 13
// speedup vs baseline: 4.3102x; 1.1382x over previous
#include <cuda_runtime.h>
#include <cuda_bf16.h>
#include <math.h>
#include <stdint.h>

#define DD 256
#define LL 128
#define NEG_SLOPE 0.2f
#define LN_EPS 1e-5f
#define ASTR 264            // A smem row stride in bf16 halves
#define WSTR 40             // W k32-slice row stride in halves (80B rows, LDSM-clean)

// K1 smem layout (dynamic):
#define A_HI 0                               // [64][264] bf16 = 33792 B
#define A_LO 33792
#define WBUF 67584                           // 2 buffers x (hi 10240 + lo 10240)
#define WSLC 20480                           // one buffer size
#define WLO  10240                           // lo offset within buffer
#define MISC 108544                          // floats
// misc floats: qb 256, w 256, s_part 256(4*64), p 64, red 32 = 864
static const int K1_SMEM = MISC + 864 * 4;   // 112000

// precomputed W2 bf16 hi/lo planes: [kc2 8][d 256][WSTR 40], pads 0
__device__ __align__(16) __nv_bfloat16 g_Whi[8 * 256 * WSTR];
__device__ __align__(16) __nv_bfloat16 g_Wlo[8 * 256 * WSTR];
__device__ __align__(16) float g_qb[2048L * 256];       // qb = mol@W1^T + b1 + b2
__device__ __align__(16) float g_y [2048L * 2 * 256];   // per-half unnormalized y
__device__ __align__(16) float g_st[2048L * 2 * 4];     // per-half (m, Z, sumattn)

__global__ void prep_w2(const float* __restrict__ W2) {
    const int d = blockIdx.x;
    for (int i = threadIdx.x; i < 8 * WSTR; i += blockDim.x) {
        const int kc2 = i / WSTR, k = i % WSTR;
        float v = (k < 32) ? W2[(long)d * DD + kc2 * 32 + k] : 0.f;
        __nv_bfloat16 h = __float2bfloat16(v);
        __nv_bfloat16 l = __float2bfloat16(v - __bfloat162float(h));
        g_Whi[((long)kc2 * 256 + d) * WSTR + k] = h;
        g_Wlo[((long)kc2 * 256 + d) * WSTR + k] = l;
    }
}

// qb GEMV: 16 molecules per CTA
__global__ __launch_bounds__(256)
void prep_qb(const float* __restrict__ mol, const float* __restrict__ W1,
             const float* __restrict__ b1, const float* __restrict__ b2) {
    __shared__ __align__(16) float mol_s[16 * 256];
    const int bm0 = blockIdx.x * 16;
    const int tid = threadIdx.x;
    for (int i = tid; i < 16 * 256; i += 256) mol_s[i] = mol[(long)bm0 * 256 + i];
    __syncthreads();
    const int d = tid;
    const float bb = b1[d] + b2[d];
    float acc[16];
    #pragma unroll
    for (int m = 0; m < 16; ++m) acc[m] = bb;
    const float4* w4 = (const float4*)(W1 + (long)d * 256);
    for (int k4 = 0; k4 < 64; ++k4) {
        const float4 wv = w4[k4];
        #pragma unroll
        for (int m = 0; m < 16; ++m) {
            const float4 yv = *(const float4*)(mol_s + m * 256 + k4 * 4);
            acc[m] += yv.x * wv.x + yv.y * wv.y + yv.z * wv.z + yv.w * wv.w;
        }
    }
    #pragma unroll
    for (int m = 0; m < 16; ++m) g_qb[(long)(bm0 + m) * 256 + d] = acc[m];
}

static __device__ __forceinline__ uint32_t smem_u32(const void* p) {
    uint32_t a;
    asm("{ .reg .u64 t; cvta.to.shared.u64 t, %1; cvt.u32.u64 %0, t; }"
        : "=r"(a) : "l"(p));
    return a;
}

#define CP_ASYNC16(dst, src) \
    asm volatile("cp.async.cg.shared.global [%0], [%1], 16;" :: "r"(dst), "l"(src) : "memory")
#define CP_COMMIT() asm volatile("cp.async.commit_group;" ::: "memory")
#define CP_WAIT1()  asm volatile("cp.async.wait_group 1;" ::: "memory")
#define CP_WAIT0()  asm volatile("cp.async.wait_group 0;" ::: "memory")

#define LDSM_X4(r0, r1, r2, r3, addr) \
    asm volatile("ldmatrix.sync.aligned.m8n8.x4.shared.b16 {%0,%1,%2,%3}, [%4];" \
        : "=r"(r0), "=r"(r1), "=r"(r2), "=r"(r3) : "r"(addr))
#define MMA_BF16(c, a, b0, b1) \
    asm volatile("mma.sync.aligned.m16n8k16.row.col.f32.bf16.bf16.f32 " \
        "{%0,%1,%2,%3}, {%4,%5,%6,%7}, {%8,%9}, {%0,%1,%2,%3};" \
        : "+f"((c)[0]), "+f"((c)[1]), "+f"((c)[2]), "+f"((c)[3]) \
        : "r"((a)[0]), "r"((a)[1]), "r"((a)[2]), "r"((a)[3]), "r"(b0), "r"(b1))

// K1: per-CTA = 64 atoms of one molecule. Scores -> half softmax stats + y_half.
__global__ __launch_bounds__(256, 2)
void k1_scores(const float* __restrict__ atom,    // [B,L,D]
               const float* __restrict__ attend,  // [B,L,1]
               const float* __restrict__ smask,   // [B,L,1]
               const float* __restrict__ w_align, // [D,1]
               const float* __restrict__ b_align) // [1]
{
    extern __shared__ char smem[];
    const uint32_t smb = smem_u32(smem);
    float* qb_s   = (float*)(smem + MISC);
    float* w_s    = qb_s + 256;
    float* s_part = w_s + 256;    // [4][64]
    float* p_arr  = s_part + 256; // 64
    float* red    = p_arr + 64;   // 32

    const int bx   = blockIdx.x;
    const int b    = bx >> 1;
    const int h    = bx & 1;
    const int tid  = threadIdx.x;
    const int lane = tid & 31;
    const int wid  = tid >> 5;
    const int mq   = wid >> 2;    // atom 32-row half within the 64-atom tile
    const int nq   = wid & 3;     // 32-col group within 128-col pass

    // prologue: issue W slice 0 (np=0, kc2=0) into buffer 0
    {
        const char* sH = (const char*)g_Whi;
        const char* sL = (const char*)g_Wlo;
        const uint32_t dH = smb + WBUF;
        const uint32_t dL = dH + WLO;
        for (int i = tid; i < 640; i += 256) {
            CP_ASYNC16(dH + i * 16, sH + i * 16);
            CP_ASYNC16(dL + i * 16, sL + i * 16);
        }
        CP_COMMIT();
    }

    qb_s[tid] = g_qb[(long)b * 256 + tid];
    w_s[tid]  = w_align[tid];
    const float bal = b_align[0];

    // stage A = 64 atoms as bf16 hi/lo
    const long abase = ((long)b * LL + 64 * h) * DD;
    for (int idx = tid; idx < 64 * (DD / 2); idx += 256) {
        const int r  = idx >> 7;
        const int kp = idx & 127;
        const float2 v = ((const float2*)(atom + abase + (long)r * DD))[kp];
        __nv_bfloat16 hx = __float2bfloat16(v.x);
        __nv_bfloat16 hy = __float2bfloat16(v.y);
        __nv_bfloat16 lx = __float2bfloat16(v.x - __bfloat162float(hx));
        __nv_bfloat16 ly = __float2bfloat16(v.y - __bfloat162float(hy));
        const int off = (r * ASTR + kp * 2) * 2;
        __nv_bfloat162 hv; hv.x = hx; hv.y = hy;
        __nv_bfloat162 lv; lv.x = lx; lv.y = ly;
        *(__nv_bfloat162*)(smem + A_HI + off) = hv;
        *(__nv_bfloat162*)(smem + A_LO + off) = lv;
    }

    // fragment base addresses (validated mappings)
    uint32_t addrAh[2], addrAl[2], bOff[2];
    {
        const uint32_t aColh = (lane >> 4) << 3;
        #pragma unroll
        for (int mt = 0; mt < 2; ++mt) {
            const uint32_t off = (((uint32_t)(32 * mq + 16 * mt) + (lane & 15)) * ASTR + aColh) * 2;
            addrAh[mt] = smb + A_HI + off;
            addrAl[mt] = smb + A_LO + off;
        }
        const uint32_t bIn16 = ((lane >> 4) << 3) + (lane & 7);
        const uint32_t bColh = ((lane >> 3) & 1) << 3;
        #pragma unroll
        for (int nt = 0; nt < 2; ++nt)
            bOff[nt] = (((uint32_t)(32 * nq + 16 * nt) + bIn16) * WSTR + bColh) * 2;
    }
    __syncthreads();   // A + qb + w ready (W slice 0 in flight)

    float sc[2][2] = {{0.f, 0.f}, {0.f, 0.f}};   // [mt][rowhalf]

    #pragma unroll 1
    for (int np = 0; np < 2; ++np) {
        float acc[2][4][4];
        #pragma unroll
        for (int mt = 0; mt < 2; ++mt)
            #pragma unroll
            for (int j = 0; j < 4; ++j)
                #pragma unroll
                for (int q = 0; q < 4; ++q) acc[mt][j][q] = 0.f;

        #pragma unroll 1
        for (int kc2 = 0; kc2 < 8; ++kc2) {
            const int s = np * 8 + kc2;
            __syncthreads();       // all warps done with slice s-1 (buf (s+1)&1)
            if (s + 1 < 16) {      // issue slice s+1 into the other buffer
                const int np2 = (s + 1) >> 3, kc2n = (s + 1) & 7;
                const char* sH = (const char*)(g_Whi + ((long)kc2n * 256 + np2 * 128) * WSTR);
                const char* sL = (const char*)(g_Wlo + ((long)kc2n * 256 + np2 * 128) * WSTR);
                const uint32_t dH = smb + WBUF + ((s + 1) & 1) * WSLC;
                const uint32_t dL = dH + WLO;
                for (int i = tid; i < 640; i += 256) {
                    CP_ASYNC16(dH + i * 16, sH + i * 16);
                    CP_ASYNC16(dL + i * 16, sL + i * 16);
                }
                CP_COMMIT();
                CP_WAIT1();        // slice s complete (s+1 in flight)
            } else {
                CP_WAIT0();
            }
            __syncthreads();       // slice s visible to all warps

            const uint32_t wbase = smb + WBUF + (s & 1) * WSLC;
            const uint32_t addrBh0 = wbase + bOff[0];
            const uint32_t addrBh1 = wbase + bOff[1];
            const uint32_t addrBl0 = wbase + WLO + bOff[0];
            const uint32_t addrBl1 = wbase + WLO + bOff[1];
            const uint32_t aks = (uint32_t)kc2 * 64;     // k32 = 64 B in A rows

            uint32_t fAh[2][2][4], fAl[2][2][4], fBh[2][2][4], fBl[2][2][4];
            #define LOADF(buf, ks) do {                                          \
                const uint32_t koA = aks + (uint32_t)(ks) * 32;                  \
                const uint32_t koB = (uint32_t)(ks) * 32;                        \
                LDSM_X4(fAh[buf][0][0], fAh[buf][0][1], fAh[buf][0][2], fAh[buf][0][3], addrAh[0] + koA); \
                LDSM_X4(fAh[buf][1][0], fAh[buf][1][1], fAh[buf][1][2], fAh[buf][1][3], addrAh[1] + koA); \
                LDSM_X4(fAl[buf][0][0], fAl[buf][0][1], fAl[buf][0][2], fAl[buf][0][3], addrAl[0] + koA); \
                LDSM_X4(fAl[buf][1][0], fAl[buf][1][1], fAl[buf][1][2], fAl[buf][1][3], addrAl[1] + koA); \
                LDSM_X4(fBh[buf][0][0], fBh[buf][0][1], fBh[buf][0][2], fBh[buf][0][3], addrBh0 + koB); \
                LDSM_X4(fBh[buf][1][0], fBh[buf][1][1], fBh[buf][1][2], fBh[buf][1][3], addrBh1 + koB); \
                LDSM_X4(fBl[buf][0][0], fBl[buf][0][1], fBl[buf][0][2], fBl[buf][0][3], addrBl0 + koB); \
                LDSM_X4(fBl[buf][1][0], fBl[buf][1][1], fBl[buf][1][2], fBl[buf][1][3], addrBl1 + koB); \
            } while (0)

            LOADF(0, 0);
            #pragma unroll
            for (int ks = 0; ks < 2; ++ks) {
                const int cur = ks & 1;
                if (ks < 1) LOADF(1, 1);
                #pragma unroll
                for (int mt = 0; mt < 2; ++mt)
                    #pragma unroll
                    for (int nt = 0; nt < 2; ++nt) {
                        float* A0 = acc[mt][2 * nt + 0];
                        float* A1 = acc[mt][2 * nt + 1];
                        MMA_BF16(A0, fAh[cur][mt], fBh[cur][nt][0], fBh[cur][nt][1]);
                        MMA_BF16(A0, fAl[cur][mt], fBh[cur][nt][0], fBh[cur][nt][1]);
                        MMA_BF16(A0, fAh[cur][mt], fBl[cur][nt][0], fBl[cur][nt][1]);
                        MMA_BF16(A1, fAh[cur][mt], fBh[cur][nt][2], fBh[cur][nt][3]);
                        MMA_BF16(A1, fAl[cur][mt], fBh[cur][nt][2], fBh[cur][nt][3]);
                        MMA_BF16(A1, fAh[cur][mt], fBl[cur][nt][2], fBl[cur][nt][3]);
                    }
            }
            #undef LOADF
        }

        // fold leakyrelu(qb + S) * w_align into per-row partials
        #pragma unroll
        for (int mt = 0; mt < 2; ++mt)
            #pragma unroll
            for (int j = 0; j < 4; ++j) {
                const int c = np * 128 + nq * 32 + (j >> 1) * 16 + (j & 1) * 8 + (lane & 3) * 2;
                const float q0 = qb_s[c], q1 = qb_s[c + 1];
                const float w0 = w_s[c],  w1 = w_s[c + 1];
                float v;
                v = q0 + acc[mt][j][0]; v = (v >= 0.f) ? v : NEG_SLOPE * v; sc[mt][0] += v * w0;
                v = q1 + acc[mt][j][1]; v = (v >= 0.f) ? v : NEG_SLOPE * v; sc[mt][0] += v * w1;
                v = q0 + acc[mt][j][2]; v = (v >= 0.f) ? v : NEG_SLOPE * v; sc[mt][1] += v * w0;
                v = q1 + acc[mt][j][3]; v = (v >= 0.f) ? v : NEG_SLOPE * v; sc[mt][1] += v * w1;
            }
    }

    // quad-reduce; unique (nq,row) writer into s_part[4][64]
    #pragma unroll
    for (int mt = 0; mt < 2; ++mt)
        #pragma unroll
        for (int rh = 0; rh < 2; ++rh) {
            float t = sc[mt][rh];
            t += __shfl_xor_sync(0xffffffffu, t, 1);
            t += __shfl_xor_sync(0xffffffffu, t, 2);
            if ((lane & 3) == 0)
                s_part[nq * 64 + 32 * mq + 16 * mt + (lane >> 2) + 8 * rh] = t;
        }
    __syncthreads();

    // half-softmax stats over 64 atoms
    {
        float v = (tid < 64)
                ? (bal + (s_part[tid] + s_part[64 + tid])
                       + (s_part[128 + tid] + s_part[192 + tid])
                       + smask[(long)b * LL + 64 * h + tid])
                : -INFINITY;
        float t = v;
        #pragma unroll
        for (int off = 16; off; off >>= 1)
            t = fmaxf(t, __shfl_xor_sync(0xffffffffu, t, off));
        if (lane == 0) red[wid] = t;
        __syncthreads();
        float mx = red[0];
        #pragma unroll
        for (int w = 1; w < 8; ++w) mx = fmaxf(mx, red[w]);
        __syncthreads();

        float e = (tid < 64) ? __expf(v - mx) : 0.f;
        float att = (tid < 64) ? attend[(long)b * LL + 64 * h + tid] : 0.f;
        float pf = e * att;
        if (tid < 64) p_arr[tid] = pf;

        float ts = e;
        #pragma unroll
        for (int off = 16; off; off >>= 1)
            ts += __shfl_xor_sync(0xffffffffu, ts, off);
        if (lane == 0) red[8 + wid] = ts;
        float ta = pf;
        #pragma unroll
        for (int off = 16; off; off >>= 1)
            ta += __shfl_xor_sync(0xffffffffu, ta, off);
        if (lane == 0) red[16 + wid] = ta;
        __syncthreads();
        if (tid == 0) {
            float Z = 0.f, sa = 0.f;
            for (int w = 0; w < 8; ++w) { Z += red[8 + w]; sa += red[16 + w]; }
            float* st = g_st + (long)(b * 2 + h) * 4;
            st[0] = mx; st[1] = Z; st[2] = sa;
        }
    }
    __syncthreads();

    // y_half[k] = sum_a pf[a] * atom[a,k] (unnormalized, masked)
    {
        const float* Ab = atom + abase;
        float acc0 = 0.f, acc1 = 0.f;
        #pragma unroll 2
        for (int a = 0; a < 64; a += 2) {
            const float p0 = p_arr[a], p1 = p_arr[a + 1];
            if (p0 != 0.f) acc0 += p0 * Ab[(long)a * DD + tid];
            if (p1 != 0.f) acc1 += p1 * Ab[(long)(a + 1) * DD + tid];
        }
        g_y[((long)(b * 2 + h)) * 256 + tid] = acc0 + acc1;
    }
}

// K2: flash-combine halves + ctx GEMV + LayerNorm. 16 molecules per CTA.
__global__ __launch_bounds__(256)
void k2_tail(const float* __restrict__ W2, const float* __restrict__ b2,
             const float* __restrict__ gamma_, const float* __restrict__ beta_,
             float* __restrict__ out)
{
    __shared__ __align__(16) float y_s[16 * 256];
    __shared__ __align__(16) float ctx_s[16 * 256];
    __shared__ float cs[16][4];
    const int bm0 = blockIdx.x * 16;
    const int tid = threadIdx.x;
    const int lane = tid & 31;
    const int wid = tid >> 5;

    if (tid < 16) {
        const float* st = g_st + (long)(bm0 + tid) * 8;
        const float m0 = st[0], Z0 = st[1], sa0 = st[2];
        const float m1 = st[4], Z1 = st[5], sa1 = st[6];
        const float mx = fmaxf(m0, m1);
        const float s0 = __expf(m0 - mx), s1 = __expf(m1 - mx);
        const float Z = Z0 * s0 + Z1 * s1;
        const float c0 = s0 / Z, c1 = s1 / Z;
        cs[tid][0] = c0; cs[tid][1] = c1;
        cs[tid][2] = sa0 * c0 + sa1 * c1;   // sum of attn
    }
    __syncthreads();
    for (int i = tid; i < 16 * 256; i += 256) {
        const int m = i >> 8, k = i & 255;
        y_s[i] = g_y[(long)(bm0 + m) * 2 * 256 + k] * cs[m][0]
               + g_y[((long)(bm0 + m) * 2 + 1) * 256 + k] * cs[m][1];
    }
    __syncthreads();
    {
        const int d = tid;
        const float b2d = b2[d];
        float acc[16];
        #pragma unroll
        for (int m = 0; m < 16; ++m) acc[m] = cs[m][2] * b2d;
        const float4* w4 = (const float4*)(W2 + (long)d * 256);
        for (int k4 = 0; k4 < 64; ++k4) {
            const float4 wv = w4[k4];
            #pragma unroll
            for (int m = 0; m < 16; ++m) {
                const float4 yv = *(const float4*)(y_s + m * 256 + k4 * 4);
                acc[m] += yv.x * wv.x + yv.y * wv.y + yv.z * wv.z + yv.w * wv.w;
            }
        }
        #pragma unroll
        for (int m = 0; m < 16; ++m) ctx_s[m * 256 + d] = acc[m];
    }
    __syncthreads();
    {   // LN: warp w -> molecules 2w, 2w+1
        #pragma unroll
        for (int mm = 0; mm < 2; ++mm) {
            const int m = 2 * wid + mm;
            float vals[8];
            float s1 = 0.f;
            #pragma unroll
            for (int j = 0; j < 8; ++j) {
                vals[j] = ctx_s[m * 256 + lane + 32 * j];
                s1 += vals[j];
            }
            #pragma unroll
            for (int off = 16; off; off >>= 1)
                s1 += __shfl_xor_sync(0xffffffffu, s1, off);
            const float mu = s1 * (1.f / 256.f);
            float s2 = 0.f;
            #pragma unroll
            for (int j = 0; j < 8; ++j) {
                const float d = vals[j] - mu;
                s2 += d * d;
            }
            #pragma unroll
            for (int off = 16; off; off >>= 1)
                s2 += __shfl_xor_sync(0xffffffffu, s2, off);
            const float inv = rsqrtf(s2 * (1.f / 256.f) + LN_EPS);
            #pragma unroll
            for (int j = 0; j < 8; ++j) {
                const int d = lane + 32 * j;
                out[(long)(bm0 + m) * 256 + d] =
                    (vals[j] - mu) * inv * gamma_[d] + beta_[d];
            }
        }
    }
}

extern "C" void kernel_launch(void* const* d_in, const int* in_sizes, int n_in,
                              void* d_out, int out_size)
{
    const float* mol     = (const float*)d_in[0];
    const float* atom    = (const float*)d_in[1];
    const float* attend  = (const float*)d_in[2];
    const float* smask   = (const float*)d_in[3];
    const float* W1      = (const float*)d_in[4];
    const float* b1      = (const float*)d_in[5];
    const float* W2      = (const float*)d_in[6];
    const float* b2      = (const float*)d_in[7];
    const float* w_align = (const float*)d_in[8];
    const float* b_align = (const float*)d_in[9];
    const float* gamma_  = (const float*)d_in[10];
    const float* beta_   = (const float*)d_in[11];
    float* out = (float*)d_out;

    const int B = in_sizes[0] / DD;

    prep_w2<<<256, 128>>>(W2);
    prep_qb<<<B / 16, 256>>>(mol, W1, b1, b2);

    cudaFuncSetAttribute(k1_scores,
                         cudaFuncAttributeMaxDynamicSharedMemorySize, K1_SMEM);
    k1_scores<<<B * 2, 256, K1_SMEM>>>(atom, attend, smask, w_align, b_align);

    k2_tail<<<B / 16, 256>>>(W2, b2, gamma_, beta_, out);
}

// round 14
// speedup vs baseline: 4.9119x; 1.1396x over previous
#include <cuda_runtime.h>
#include <cuda_bf16.h>
#include <math.h>
#include <stdint.h>

#define DD 256
#define LL 128
#define NEG_SLOPE 0.2f
#define LN_EPS 1e-5f
#define ASTR 264            // A smem row stride in bf16 halves

// K1 smem: A hi/lo + misc floats
#define A_HI 0                               // [64][264] bf16 = 33792 B
#define A_LO 33792
#define MISC 67584                           // floats
// misc floats: qb 256, w 256, s_part 256(4*64), p 64, red 32 = 864
static const int K1_SMEM = MISC + 864 * 4;   // 71040

// W2 in MMA-fragment-major layout (exact ldmatrix register image):
// [plane 2 (hi/lo)][ks 16][ng 16][lane 32][16B]  = 256 KB
// plane stride 131072 B, ks stride 8192 B, ng stride 512 B
__device__ __align__(16) __nv_bfloat16 g_Wf[131072];
__device__ __align__(16) float g_qb[2048L * 256];       // qb = mol@W1^T + b1 + b2
__device__ __align__(16) float g_y [2048L * 2 * 256];   // per-half unnormalized y
__device__ __align__(16) float g_st[2048L * 2 * 4];     // per-half (m, Z, sumattn)

// Build the fragment table. For unit (plane, ks, ng), lane t holds
// b0=(n0+t/4, k0+2m..+1), b1=(n0+t/4, k0+8+2m..), b2=(n0+8+t/4, k0+2m..),
// b3=(n0+8+t/4, k0+8+2m..)   with m = t%4  (PTX m8n8 ldmatrix distribution)
__global__ void prep_wf(const float* __restrict__ W2) {
    const int idx  = blockIdx.x * 256 + threadIdx.x;   // 0..16383
    const int lane = idx & 31;
    const int unit = idx >> 5;                          // 0..511
    const int ng    = unit & 15;
    const int ks    = (unit >> 4) & 15;
    const int plane = unit >> 8;
    const int n0 = ng * 16, k0 = ks * 16;
    const int r = lane >> 2, m = lane & 3;
    __nv_bfloat16 vals[8];
    int c = 0;
    #pragma unroll
    for (int rr = 0; rr < 2; ++rr)
        #pragma unroll
        for (int kk = 0; kk < 2; ++kk)
            #pragma unroll
            for (int e = 0; e < 2; ++e) {
                const float v = W2[(long)(n0 + 8 * rr + r) * DD + k0 + 8 * kk + 2 * m + e];
                const __nv_bfloat16 h = __float2bfloat16(v);
                vals[c++] = (plane == 0) ? h
                          : __float2bfloat16(v - __bfloat162float(h));
            }
    *(uint4*)((char*)g_Wf + (long)idx * 16) = *(uint4*)vals;
}

// qb GEMV: 16 molecules per CTA
__global__ __launch_bounds__(256)
void prep_qb(const float* __restrict__ mol, const float* __restrict__ W1,
             const float* __restrict__ b1, const float* __restrict__ b2) {
    __shared__ __align__(16) float mol_s[16 * 256];
    const int bm0 = blockIdx.x * 16;
    const int tid = threadIdx.x;
    for (int i = tid; i < 16 * 256; i += 256) mol_s[i] = mol[(long)bm0 * 256 + i];
    __syncthreads();
    const int d = tid;
    const float bb = b1[d] + b2[d];
    float acc[16];
    #pragma unroll
    for (int m = 0; m < 16; ++m) acc[m] = bb;
    const float4* w4 = (const float4*)(W1 + (long)d * 256);
    for (int k4 = 0; k4 < 64; ++k4) {
        const float4 wv = w4[k4];
        #pragma unroll
        for (int m = 0; m < 16; ++m) {
            const float4 yv = *(const float4*)(mol_s + m * 256 + k4 * 4);
            acc[m] += yv.x * wv.x + yv.y * wv.y + yv.z * wv.z + yv.w * wv.w;
        }
    }
    #pragma unroll
    for (int m = 0; m < 16; ++m) g_qb[(long)(bm0 + m) * 256 + d] = acc[m];
}

static __device__ __forceinline__ uint32_t smem_u32(const void* p) {
    uint32_t a;
    asm("{ .reg .u64 t; cvta.to.shared.u64 t, %1; cvt.u32.u64 %0, t; }"
        : "=r"(a) : "l"(p));
    return a;
}

#define LDSM_X4(r0, r1, r2, r3, addr) \
    asm volatile("ldmatrix.sync.aligned.m8n8.x4.shared.b16 {%0,%1,%2,%3}, [%4];" \
        : "=r"(r0), "=r"(r1), "=r"(r2), "=r"(r3) : "r"(addr))
#define MMA_BF16(c, a, b0, b1) \
    asm volatile("mma.sync.aligned.m16n8k16.row.col.f32.bf16.bf16.f32 " \
        "{%0,%1,%2,%3}, {%4,%5,%6,%7}, {%8,%9}, {%0,%1,%2,%3};" \
        : "+f"((c)[0]), "+f"((c)[1]), "+f"((c)[2]), "+f"((c)[3]) \
        : "r"((a)[0]), "r"((a)[1]), "r"((a)[2]), "r"((a)[3]), "r"(b0), "r"(b1))

// K1: per-CTA = 64 atoms of one molecule. Barrier-free MMA mainloop.
__global__ __launch_bounds__(256, 2)
void k1_scores(const float* __restrict__ atom,    // [B,L,D]
               const float* __restrict__ attend,  // [B,L,1]
               const float* __restrict__ smask,   // [B,L,1]
               const float* __restrict__ w_align, // [D,1]
               const float* __restrict__ b_align) // [1]
{
    extern __shared__ char smem[];
    const uint32_t smb = smem_u32(smem);
    float* qb_s   = (float*)(smem + MISC);
    float* w_s    = qb_s + 256;
    float* s_part = w_s + 256;    // [4][64]
    float* p_arr  = s_part + 256; // 64
    float* red    = p_arr + 64;   // 32

    const int bx   = blockIdx.x;
    const int b    = bx >> 1;
    const int h    = bx & 1;
    const int tid  = threadIdx.x;
    const int lane = tid & 31;
    const int wid  = tid >> 5;
    const int mq   = wid >> 2;    // atom 32-row half within the 64-atom tile
    const int nq   = wid & 3;     // 32-col group within 128-col pass

    qb_s[tid] = g_qb[(long)b * 256 + tid];
    w_s[tid]  = w_align[tid];
    const float bal = b_align[0];

    // stage A = 64 atoms as bf16 hi/lo
    const long abase = ((long)b * LL + 64 * h) * DD;
    for (int idx = tid; idx < 64 * (DD / 2); idx += 256) {
        const int r  = idx >> 7;
        const int kp = idx & 127;
        const float2 v = ((const float2*)(atom + abase + (long)r * DD))[kp];
        __nv_bfloat16 hx = __float2bfloat16(v.x);
        __nv_bfloat16 hy = __float2bfloat16(v.y);
        __nv_bfloat16 lx = __float2bfloat16(v.x - __bfloat162float(hx));
        __nv_bfloat16 ly = __float2bfloat16(v.y - __bfloat162float(hy));
        const int off = (r * ASTR + kp * 2) * 2;
        __nv_bfloat162 hv; hv.x = hx; hv.y = hy;
        __nv_bfloat162 lv; lv.x = lx; lv.y = ly;
        *(__nv_bfloat162*)(smem + A_HI + off) = hv;
        *(__nv_bfloat162*)(smem + A_LO + off) = lv;
    }

    // A fragment base addresses (validated mappings)
    uint32_t addrAh[2], addrAl[2];
    {
        const uint32_t aColh = (lane >> 4) << 3;
        #pragma unroll
        for (int mt = 0; mt < 2; ++mt) {
            const uint32_t off = (((uint32_t)(32 * mq + 16 * mt) + (lane & 15)) * ASTR + aColh) * 2;
            addrAh[mt] = smb + A_HI + off;
            addrAl[mt] = smb + A_LO + off;
        }
    }
    // B fragment gmem base (hi plane, np=0): ng = nq*2 + nt
    const char* bB0 = (const char*)g_Wf + ((uint32_t)(nq * 2 + 0)) * 512 + (uint32_t)lane * 16;
    const char* bB1 = (const char*)g_Wf + ((uint32_t)(nq * 2 + 1)) * 512 + (uint32_t)lane * 16;

    __syncthreads();   // A + qb + w ready — last barrier before the tail

    float sc[2][2] = {{0.f, 0.f}, {0.f, 0.f}};   // [mt][rowhalf]

    #pragma unroll 1
    for (int np = 0; np < 2; ++np) {
        float acc[2][4][4];
        #pragma unroll
        for (int mt = 0; mt < 2; ++mt)
            #pragma unroll
            for (int j = 0; j < 4; ++j)
                #pragma unroll
                for (int q = 0; q < 4; ++q) acc[mt][j][q] = 0.f;

        const char* b0 = bB0 + np * 4096;    // ng stride 512, np adds 8 ngs
        const char* b1 = bB1 + np * 4096;

        // prefetch ks=0 B fragments (hi+lo planes)
        uint4 cBh0 = *(const uint4*)(b0);
        uint4 cBh1 = *(const uint4*)(b1);
        uint4 cBl0 = *(const uint4*)(b0 + 131072);
        uint4 cBl1 = *(const uint4*)(b1 + 131072);

        #pragma unroll
        for (int ks = 0; ks < 16; ++ks) {
            uint4 nBh0, nBh1, nBl0, nBl1;
            if (ks < 15) {
                const int o = (ks + 1) * 8192;
                nBh0 = *(const uint4*)(b0 + o);
                nBh1 = *(const uint4*)(b1 + o);
                nBl0 = *(const uint4*)(b0 + 131072 + o);
                nBl1 = *(const uint4*)(b1 + 131072 + o);
            }
            uint32_t fAh[2][4], fAl[2][4];
            const uint32_t koA = (uint32_t)ks * 32;
            LDSM_X4(fAh[0][0], fAh[0][1], fAh[0][2], fAh[0][3], addrAh[0] + koA);
            LDSM_X4(fAh[1][0], fAh[1][1], fAh[1][2], fAh[1][3], addrAh[1] + koA);
            LDSM_X4(fAl[0][0], fAl[0][1], fAl[0][2], fAl[0][3], addrAl[0] + koA);
            LDSM_X4(fAl[1][0], fAl[1][1], fAl[1][2], fAl[1][3], addrAl[1] + koA);

            #pragma unroll
            for (int mt = 0; mt < 2; ++mt) {
                float* A0 = acc[mt][0];
                float* A1 = acc[mt][1];
                float* A2 = acc[mt][2];
                float* A3 = acc[mt][3];
                MMA_BF16(A0, fAh[mt], cBh0.x, cBh0.y);
                MMA_BF16(A0, fAl[mt], cBh0.x, cBh0.y);
                MMA_BF16(A0, fAh[mt], cBl0.x, cBl0.y);
                MMA_BF16(A1, fAh[mt], cBh0.z, cBh0.w);
                MMA_BF16(A1, fAl[mt], cBh0.z, cBh0.w);
                MMA_BF16(A1, fAh[mt], cBl0.z, cBl0.w);
                MMA_BF16(A2, fAh[mt], cBh1.x, cBh1.y);
                MMA_BF16(A2, fAl[mt], cBh1.x, cBh1.y);
                MMA_BF16(A2, fAh[mt], cBl1.x, cBl1.y);
                MMA_BF16(A3, fAh[mt], cBh1.z, cBh1.w);
                MMA_BF16(A3, fAl[mt], cBh1.z, cBh1.w);
                MMA_BF16(A3, fAh[mt], cBl1.z, cBl1.w);
            }
            cBh0 = nBh0; cBh1 = nBh1; cBl0 = nBl0; cBl1 = nBl1;
        }

        // fold leakyrelu(qb + S) * w_align into per-row partials
        // acc[mt][j]: col = np*128 + nq*32 + (j>>1)*16 + (j&1)*8 + (lane&3)*2
        #pragma unroll
        for (int mt = 0; mt < 2; ++mt)
            #pragma unroll
            for (int j = 0; j < 4; ++j) {
                const int c = np * 128 + nq * 32 + (j >> 1) * 16 + (j & 1) * 8 + (lane & 3) * 2;
                const float q0 = qb_s[c], q1 = qb_s[c + 1];
                const float w0 = w_s[c],  w1 = w_s[c + 1];
                float v;
                v = q0 + acc[mt][j][0]; v = (v >= 0.f) ? v : NEG_SLOPE * v; sc[mt][0] += v * w0;
                v = q1 + acc[mt][j][1]; v = (v >= 0.f) ? v : NEG_SLOPE * v; sc[mt][0] += v * w1;
                v = q0 + acc[mt][j][2]; v = (v >= 0.f) ? v : NEG_SLOPE * v; sc[mt][1] += v * w0;
                v = q1 + acc[mt][j][3]; v = (v >= 0.f) ? v : NEG_SLOPE * v; sc[mt][1] += v * w1;
            }
    }

    // quad-reduce; unique (nq,row) writer into s_part[4][64]
    #pragma unroll
    for (int mt = 0; mt < 2; ++mt)
        #pragma unroll
        for (int rh = 0; rh < 2; ++rh) {
            float t = sc[mt][rh];
            t += __shfl_xor_sync(0xffffffffu, t, 1);
            t += __shfl_xor_sync(0xffffffffu, t, 2);
            if ((lane & 3) == 0)
                s_part[nq * 64 + 32 * mq + 16 * mt + (lane >> 2) + 8 * rh] = t;
        }
    __syncthreads();

    // half-softmax stats over 64 atoms
    {
        float v = (tid < 64)
                ? (bal + (s_part[tid] + s_part[64 + tid])
                       + (s_part[128 + tid] + s_part[192 + tid])
                       + smask[(long)b * LL + 64 * h + tid])
                : -INFINITY;
        float t = v;
        #pragma unroll
        for (int off = 16; off; off >>= 1)
            t = fmaxf(t, __shfl_xor_sync(0xffffffffu, t, off));
        if (lane == 0) red[wid] = t;
        __syncthreads();
        float mx = red[0];
        #pragma unroll
        for (int w = 1; w < 8; ++w) mx = fmaxf(mx, red[w]);
        __syncthreads();

        float e = (tid < 64) ? __expf(v - mx) : 0.f;
        float att = (tid < 64) ? attend[(long)b * LL + 64 * h + tid] : 0.f;
        float pf = e * att;
        if (tid < 64) p_arr[tid] = pf;

        float ts = e;
        #pragma unroll
        for (int off = 16; off; off >>= 1)
            ts += __shfl_xor_sync(0xffffffffu, ts, off);
        if (lane == 0) red[8 + wid] = ts;
        float ta = pf;
        #pragma unroll
        for (int off = 16; off; off >>= 1)
            ta += __shfl_xor_sync(0xffffffffu, ta, off);
        if (lane == 0) red[16 + wid] = ta;
        __syncthreads();
        if (tid == 0) {
            float Z = 0.f, sa = 0.f;
            for (int w = 0; w < 8; ++w) { Z += red[8 + w]; sa += red[16 + w]; }
            float* st = g_st + (long)(b * 2 + h) * 4;
            st[0] = mx; st[1] = Z; st[2] = sa;
        }
    }
    __syncthreads();

    // y_half[k] = sum_a pf[a] * atom[a,k] (unnormalized, masked)
    {
        const float* Ab = atom + abase;
        float acc0 = 0.f, acc1 = 0.f;
        #pragma unroll 2
        for (int a = 0; a < 64; a += 2) {
            const float p0 = p_arr[a], p1 = p_arr[a + 1];
            if (p0 != 0.f) acc0 += p0 * Ab[(long)a * DD + tid];
            if (p1 != 0.f) acc1 += p1 * Ab[(long)(a + 1) * DD + tid];
        }
        g_y[((long)(b * 2 + h)) * 256 + tid] = acc0 + acc1;
    }
}

// K2: flash-combine halves + ctx GEMV + LayerNorm. 4 molecules per CTA.
__global__ __launch_bounds__(256)
void k2_tail(const float* __restrict__ W2, const float* __restrict__ b2,
             const float* __restrict__ gamma_, const float* __restrict__ beta_,
             float* __restrict__ out)
{
    __shared__ __align__(16) float y_s[4 * 256];
    __shared__ __align__(16) float ctx_s[4 * 256];
    __shared__ float cs[4][4];
    const int bm0 = blockIdx.x * 4;
    const int tid = threadIdx.x;
    const int lane = tid & 31;
    const int wid = tid >> 5;

    if (tid < 4) {
        const float* st = g_st + (long)(bm0 + tid) * 8;
        const float m0 = st[0], Z0 = st[1], sa0 = st[2];
        const float m1 = st[4], Z1 = st[5], sa1 = st[6];
        const float mx = fmaxf(m0, m1);
        const float s0 = __expf(m0 - mx), s1 = __expf(m1 - mx);
        const float Z = Z0 * s0 + Z1 * s1;
        const float c0 = s0 / Z, c1 = s1 / Z;
        cs[tid][0] = c0; cs[tid][1] = c1;
        cs[tid][2] = sa0 * c0 + sa1 * c1;   // sum of attn
    }
    __syncthreads();
    for (int i = tid; i < 4 * 256; i += 256) {
        const int m = i >> 8, k = i & 255;
        y_s[i] = g_y[(long)(bm0 + m) * 2 * 256 + k] * cs[m][0]
               + g_y[((long)(bm0 + m) * 2 + 1) * 256 + k] * cs[m][1];
    }
    __syncthreads();
    {
        const int d = tid;
        const float b2d = b2[d];
        float acc[4];
        #pragma unroll
        for (int m = 0; m < 4; ++m) acc[m] = cs[m][2] * b2d;
        const float4* w4 = (const float4*)(W2 + (long)d * 256);
        #pragma unroll 4
        for (int k4 = 0; k4 < 64; ++k4) {
            const float4 wv = w4[k4];
            #pragma unroll
            for (int m = 0; m < 4; ++m) {
                const float4 yv = *(const float4*)(y_s + m * 256 + k4 * 4);
                acc[m] += yv.x * wv.x + yv.y * wv.y + yv.z * wv.z + yv.w * wv.w;
            }
        }
        #pragma unroll
        for (int m = 0; m < 4; ++m) ctx_s[m * 256 + d] = acc[m];
    }
    __syncthreads();
    if (wid < 4) {   // LN: warp w -> molecule w
        const int m = wid;
        float vals[8];
        float s1 = 0.f;
        #pragma unroll
        for (int j = 0; j < 8; ++j) {
            vals[j] = ctx_s[m * 256 + lane + 32 * j];
            s1 += vals[j];
        }
        #pragma unroll
        for (int off = 16; off; off >>= 1)
            s1 += __shfl_xor_sync(0xffffffffu, s1, off);
        const float mu = s1 * (1.f / 256.f);
        float s2 = 0.f;
        #pragma unroll
        for (int j = 0; j < 8; ++j) {
            const float d = vals[j] - mu;
            s2 += d * d;
        }
        #pragma unroll
        for (int off = 16; off; off >>= 1)
            s2 += __shfl_xor_sync(0xffffffffu, s2, off);
        const float inv = rsqrtf(s2 * (1.f / 256.f) + LN_EPS);
        #pragma unroll
        for (int j = 0; j < 8; ++j) {
            const int d = lane + 32 * j;
            out[(long)(bm0 + m) * 256 + d] =
                (vals[j] - mu) * inv * gamma_[d] + beta_[d];
        }
    }
}

extern "C" void kernel_launch(void* const* d_in, const int* in_sizes, int n_in,
                              void* d_out, int out_size)
{
    const float* mol     = (const float*)d_in[0];
    const float* atom    = (const float*)d_in[1];
    const float* attend  = (const float*)d_in[2];
    const float* smask   = (const float*)d_in[3];
    const float* W1      = (const float*)d_in[4];
    const float* b1      = (const float*)d_in[5];
    const float* W2      = (const float*)d_in[6];
    const float* b2      = (const float*)d_in[7];
    const float* w_align = (const float*)d_in[8];
    const float* b_align = (const float*)d_in[9];
    const float* gamma_  = (const float*)d_in[10];
    const float* beta_   = (const float*)d_in[11];
    float* out = (float*)d_out;

    const int B = in_sizes[0] / DD;

    prep_wf<<<64, 256>>>(W2);
    prep_qb<<<B / 16, 256>>>(mol, W1, b1, b2);

    cudaFuncSetAttribute(k1_scores,
                         cudaFuncAttributeMaxDynamicSharedMemorySize, K1_SMEM);
    k1_scores<<<B * 2, 256, K1_SMEM>>>(atom, attend, smask, w_align, b_align);

    k2_tail<<<B / 4, 256>>>(W2, b2, gamma_, beta_, out);
}